// round 3
// baseline (speedup 1.0000x reference)
#include <cuda_runtime.h>
#include <cstdint>

#define D1 128
#define TM 64
#define KC 32

// Scratch: node feature accumulator [N=100000, 128] fp32 (51.2 MB)
__device__ float g_nf[100000 * 128];

typedef unsigned long long u64;

__device__ __forceinline__ u64 ffma2(u64 a, u64 b, u64 c) {
    u64 d;
    asm("fma.rn.f32x2 %0, %1, %2, %3;" : "=l"(d) : "l"(a), "l"(b), "l"(c));
    return d;
}
__device__ __forceinline__ u64 bcast2(float x) {
    u64 r;
    unsigned int xi = __float_as_uint(x);
    asm("mov.b64 %0, {%1, %1};" : "=l"(r) : "r"(xi));
    return r;
}
__device__ __forceinline__ float2 unpack2(u64 p) {
    unsigned int lo, hi;
    asm("mov.b64 {%0, %1}, %2;" : "=r"(lo), "=r"(hi) : "l"(p));
    return make_float2(__uint_as_float(lo), __uint_as_float(hi));
}

// ---------------------------------------------------------------------------
// Kernel 0: zero the nf accumulator
// ---------------------------------------------------------------------------
__global__ void k_zero(int n4) {
    int i = blockIdx.x * blockDim.x + threadIdx.x;
    if (i < n4) reinterpret_cast<float4*>(g_nf)[i] = make_float4(0.f, 0.f, 0.f, 0.f);
}

// ---------------------------------------------------------------------------
// Kernel 1: fused  BN -> [T,128]x[128,256] -> ReLU -> x[256,256] -> scatter
// Block: 64 tokens x 256 cols. 256 threads; thread tile 8 rows x 8 cols
// (4 f32x2 column-pairs, cols = 2*lane + 64*j -> conflict-free LDS.64).
// ---------------------------------------------------------------------------
__global__ void __launch_bounds__(256, 1) k_mlp1_scatter(
    const float* __restrict__ x,
    const int* __restrict__ tok,              // [2*T] int32 (JAX x64 disabled)
    const float* __restrict__ bn_g, const float* __restrict__ bn_b,
    const float* __restrict__ bn_m, const float* __restrict__ bn_v,
    const float* __restrict__ W1, const float* __restrict__ b1,   // [256,128],[256]
    const float* __restrict__ W2, const float* __restrict__ b2,   // [256,256],[256]
    int T)
{
    extern __shared__ float sm[];
    float* xs  = sm;                   // 64*128  = 8192 floats
    float* as_ = sm + 8192;            // 64*256  = 16384
    float* ws  = sm + 8192 + 16384;    // 32*256  = 8192
    float* sc  = ws + 8192;            // 128
    float* sh  = sc + 128;             // 128

    const int tid  = threadIdx.x;
    const int rowt = tid >> 5;         // 0..7
    const int colt = tid & 31;         // 0..31
    const int t0   = blockIdx.x * TM;

    // fold BN: xn = x*sc + sh
    if (tid < 128) {
        float a = bn_g[tid] * rsqrtf(bn_v[tid] + 1e-5f);
        sc[tid] = a;
        sh[tid] = bn_b[tid] - bn_m[tid] * a;
    }
    __syncthreads();

    // load + normalize x tile (64x128), zero-fill tail rows
    #pragma unroll
    for (int it = 0; it < 8; ++it) {
        int idx = tid + it * 256;      // float4 index 0..2047
        int r = idx >> 5;
        int c = (idx & 31) * 4;
        float4 val = make_float4(0.f, 0.f, 0.f, 0.f);
        if (t0 + r < T) val = *reinterpret_cast<const float4*>(x + (size_t)(t0 + r) * D1 + c);
        val.x = val.x * sc[c]     + sh[c];
        val.y = val.y * sc[c + 1] + sh[c + 1];
        val.z = val.z * sc[c + 2] + sh[c + 2];
        val.w = val.w * sc[c + 3] + sh[c + 3];
        *reinterpret_cast<float4*>(xs + r * D1 + c) = val;
    }

    // ---------------- GEMM1: a = relu(xn @ W1^T + b1) ----------------
    u64 acc[8][4];
    #pragma unroll
    for (int j = 0; j < 4; ++j) {
        u64 bb = *reinterpret_cast<const u64*>(b1 + 2 * colt + 64 * j);
        #pragma unroll
        for (int i = 0; i < 8; ++i) acc[i][j] = bb;
    }

    for (int k0 = 0; k0 < 128; k0 += KC) {
        __syncthreads();   // xs ready (first iter) / ws consumed (later iters)
        {   // stream W1 chunk, transposed: ws[kk][n] = W1[n][k0+kk]
            const float* wr = W1 + (size_t)tid * 128 + k0;
            #pragma unroll
            for (int q = 0; q < KC / 4; ++q) {
                float4 w = *reinterpret_cast<const float4*>(wr + q * 4);
                ws[(q * 4 + 0) * 256 + tid] = w.x;
                ws[(q * 4 + 1) * 256 + tid] = w.y;
                ws[(q * 4 + 2) * 256 + tid] = w.z;
                ws[(q * 4 + 3) * 256 + tid] = w.w;
            }
        }
        __syncthreads();
        #pragma unroll 8
        for (int kk = 0; kk < KC; ++kk) {
            u64 bf[4];
            #pragma unroll
            for (int j = 0; j < 4; ++j)
                bf[j] = *reinterpret_cast<const u64*>(ws + kk * 256 + 2 * colt + 64 * j);
            #pragma unroll
            for (int i = 0; i < 8; ++i) {
                u64 a2 = bcast2(xs[(rowt + 8 * i) * D1 + k0 + kk]);
                #pragma unroll
                for (int j = 0; j < 4; ++j) acc[i][j] = ffma2(a2, bf[j], acc[i][j]);
            }
        }
    }

    // relu -> shared a tile
    #pragma unroll
    for (int i = 0; i < 8; ++i) {
        #pragma unroll
        for (int j = 0; j < 4; ++j) {
            float2 f = unpack2(acc[i][j]);
            f.x = fmaxf(f.x, 0.f);
            f.y = fmaxf(f.y, 0.f);
            *reinterpret_cast<float2*>(as_ + (rowt + 8 * i) * 256 + 2 * colt + 64 * j) = f;
        }
    }

    // ---------------- GEMM2: y = a @ W2^T + b2 ----------------
    u64 acc2[8][4];
    #pragma unroll
    for (int j = 0; j < 4; ++j) {
        u64 bb = *reinterpret_cast<const u64*>(b2 + 2 * colt + 64 * j);
        #pragma unroll
        for (int i = 0; i < 8; ++i) acc2[i][j] = bb;
    }

    for (int k0 = 0; k0 < 256; k0 += KC) {
        __syncthreads();   // as_ ready (first iter) / ws consumed
        {
            const float* wr = W2 + (size_t)tid * 256 + k0;
            #pragma unroll
            for (int q = 0; q < KC / 4; ++q) {
                float4 w = *reinterpret_cast<const float4*>(wr + q * 4);
                ws[(q * 4 + 0) * 256 + tid] = w.x;
                ws[(q * 4 + 1) * 256 + tid] = w.y;
                ws[(q * 4 + 2) * 256 + tid] = w.z;
                ws[(q * 4 + 3) * 256 + tid] = w.w;
            }
        }
        __syncthreads();
        #pragma unroll 8
        for (int kk = 0; kk < KC; ++kk) {
            u64 bf[4];
            #pragma unroll
            for (int j = 0; j < 4; ++j)
                bf[j] = *reinterpret_cast<const u64*>(ws + kk * 256 + 2 * colt + 64 * j);
            #pragma unroll
            for (int i = 0; i < 8; ++i) {
                u64 a2 = bcast2(as_[(rowt + 8 * i) * 256 + k0 + kk]);
                #pragma unroll
                for (int j = 0; j < 4; ++j) acc2[i][j] = ffma2(a2, bf[j], acc2[i][j]);
            }
        }
    }

    // ---------------- scatter: nf[i0] += y[:, :128]; nf[i1] += y[:, 128:] ----
    #pragma unroll
    for (int i = 0; i < 8; ++i) {
        int r = rowt + 8 * i;
        int t = t0 + r;
        if (t >= T) continue;
        int i0 = tok[t];
        int i1 = tok[T + t];
        float* base0 = g_nf + (size_t)i0 * D1;
        float* base1 = g_nf + (size_t)i1 * D1;
        #pragma unroll
        for (int j = 0; j < 4; ++j) {
            float2 f = unpack2(acc2[i][j]);
            int c = 2 * colt + 64 * j;
            float* dst = (j < 2) ? (base0 + c) : (base1 + (c - 128));
            atomicAdd(dst, f.x);
            atomicAdd(dst + 1, f.y);
        }
    }
}

// ---------------------------------------------------------------------------
// Kernel 2: MLP2 over nf: BN -> [N,128]x[128,128] -> ReLU -> x[128,128] -> out
// Block: 64 nodes x 128 cols; thread tile 8 rows x 4 cols (2 f32x2 pairs).
// ---------------------------------------------------------------------------
__global__ void __launch_bounds__(256, 1) k_mlp2(
    const float* __restrict__ bn_g, const float* __restrict__ bn_b,
    const float* __restrict__ bn_m, const float* __restrict__ bn_v,
    const float* __restrict__ W1, const float* __restrict__ b1,   // [128,128],[128]
    const float* __restrict__ W2, const float* __restrict__ b2,   // [128,128],[128]
    float* __restrict__ out, int N)
{
    extern __shared__ float sm[];
    float* xs  = sm;                 // 64*128 = 8192
    float* as_ = sm + 8192;          // 64*128 = 8192
    float* ws  = sm + 16384;         // 32*128 = 4096
    float* sc  = ws + 4096;          // 128
    float* sh  = sc + 128;           // 128

    const int tid  = threadIdx.x;
    const int rowt = tid >> 5;
    const int colt = tid & 31;
    const int n0   = blockIdx.x * TM;

    if (tid < 128) {
        float a = bn_g[tid] * rsqrtf(bn_v[tid] + 1e-5f);
        sc[tid] = a;
        sh[tid] = bn_b[tid] - bn_m[tid] * a;
    }
    __syncthreads();

    #pragma unroll
    for (int it = 0; it < 8; ++it) {
        int idx = tid + it * 256;
        int r = idx >> 5;
        int c = (idx & 31) * 4;
        float4 val = make_float4(0.f, 0.f, 0.f, 0.f);
        if (n0 + r < N) val = *reinterpret_cast<const float4*>(g_nf + (size_t)(n0 + r) * D1 + c);
        val.x = val.x * sc[c]     + sh[c];
        val.y = val.y * sc[c + 1] + sh[c + 1];
        val.z = val.z * sc[c + 2] + sh[c + 2];
        val.w = val.w * sc[c + 3] + sh[c + 3];
        *reinterpret_cast<float4*>(xs + r * D1 + c) = val;
    }

    // GEMM1
    u64 acc[8][2];
    #pragma unroll
    for (int j = 0; j < 2; ++j) {
        u64 bb = *reinterpret_cast<const u64*>(b1 + 2 * colt + 64 * j);
        #pragma unroll
        for (int i = 0; i < 8; ++i) acc[i][j] = bb;
    }

    for (int k0 = 0; k0 < 128; k0 += KC) {
        __syncthreads();
        {   // ws[kk][n] = W1[n][k0+kk], n in 0..127, two threads per row
            int n  = tid & 127;
            int kh = (tid >> 7) * 16;
            const float* wr = W1 + (size_t)n * 128 + k0 + kh;
            #pragma unroll
            for (int q = 0; q < 4; ++q) {
                float4 w = *reinterpret_cast<const float4*>(wr + q * 4);
                ws[(kh + q * 4 + 0) * 128 + n] = w.x;
                ws[(kh + q * 4 + 1) * 128 + n] = w.y;
                ws[(kh + q * 4 + 2) * 128 + n] = w.z;
                ws[(kh + q * 4 + 3) * 128 + n] = w.w;
            }
        }
        __syncthreads();
        #pragma unroll 8
        for (int kk = 0; kk < KC; ++kk) {
            u64 bf[2];
            #pragma unroll
            for (int j = 0; j < 2; ++j)
                bf[j] = *reinterpret_cast<const u64*>(ws + kk * 128 + 2 * colt + 64 * j);
            #pragma unroll
            for (int i = 0; i < 8; ++i) {
                u64 a2 = bcast2(xs[(rowt + 8 * i) * D1 + k0 + kk]);
                #pragma unroll
                for (int j = 0; j < 2; ++j) acc[i][j] = ffma2(a2, bf[j], acc[i][j]);
            }
        }
    }

    #pragma unroll
    for (int i = 0; i < 8; ++i) {
        #pragma unroll
        for (int j = 0; j < 2; ++j) {
            float2 f = unpack2(acc[i][j]);
            f.x = fmaxf(f.x, 0.f);
            f.y = fmaxf(f.y, 0.f);
            *reinterpret_cast<float2*>(as_ + (rowt + 8 * i) * 128 + 2 * colt + 64 * j) = f;
        }
    }

    // GEMM2
    u64 acc2[8][2];
    #pragma unroll
    for (int j = 0; j < 2; ++j) {
        u64 bb = *reinterpret_cast<const u64*>(b2 + 2 * colt + 64 * j);
        #pragma unroll
        for (int i = 0; i < 8; ++i) acc2[i][j] = bb;
    }

    for (int k0 = 0; k0 < 128; k0 += KC) {
        __syncthreads();
        {
            int n  = tid & 127;
            int kh = (tid >> 7) * 16;
            const float* wr = W2 + (size_t)n * 128 + k0 + kh;
            #pragma unroll
            for (int q = 0; q < 4; ++q) {
                float4 w = *reinterpret_cast<const float4*>(wr + q * 4);
                ws[(kh + q * 4 + 0) * 128 + n] = w.x;
                ws[(kh + q * 4 + 1) * 128 + n] = w.y;
                ws[(kh + q * 4 + 2) * 128 + n] = w.z;
                ws[(kh + q * 4 + 3) * 128 + n] = w.w;
            }
        }
        __syncthreads();
        #pragma unroll 8
        for (int kk = 0; kk < KC; ++kk) {
            u64 bf[2];
            #pragma unroll
            for (int j = 0; j < 2; ++j)
                bf[j] = *reinterpret_cast<const u64*>(ws + kk * 128 + 2 * colt + 64 * j);
            #pragma unroll
            for (int i = 0; i < 8; ++i) {
                u64 a2 = bcast2(as_[(rowt + 8 * i) * 128 + k0 + kk]);
                #pragma unroll
                for (int j = 0; j < 2; ++j) acc2[i][j] = ffma2(a2, bf[j], acc2[i][j]);
            }
        }
    }

    #pragma unroll
    for (int i = 0; i < 8; ++i) {
        int r = rowt + 8 * i;
        int node = n0 + r;
        if (node >= N) continue;
        #pragma unroll
        for (int j = 0; j < 2; ++j) {
            float2 f = unpack2(acc2[i][j]);
            *reinterpret_cast<float2*>(out + (size_t)node * D1 + 2 * colt + 64 * j) = f;
        }
    }
}

// ---------------------------------------------------------------------------
extern "C" void kernel_launch(void* const* d_in, const int* in_sizes, int n_in,
                              void* d_out, int out_size) {
    const float* x    = (const float*)d_in[0];
    // d_in[1] node_features: zeroed in original model, unused
    const int*   tok  = (const int*)d_in[3];   // int32 (JAX default x64-disabled)
    const float* op_g  = (const float*)d_in[4];
    const float* op_b  = (const float*)d_in[5];
    const float* op_m  = (const float*)d_in[6];
    const float* op_v  = (const float*)d_in[7];
    const float* op_w1 = (const float*)d_in[8];
    const float* op_b1 = (const float*)d_in[9];
    const float* op_w2 = (const float*)d_in[10];
    const float* op_b2 = (const float*)d_in[11];
    const float* nm_g  = (const float*)d_in[12];
    const float* nm_b  = (const float*)d_in[13];
    const float* nm_m  = (const float*)d_in[14];
    const float* nm_v  = (const float*)d_in[15];
    const float* nm_w1 = (const float*)d_in[16];
    const float* nm_b1 = (const float*)d_in[17];
    const float* nm_w2 = (const float*)d_in[18];
    const float* nm_b2 = (const float*)d_in[19];

    int T = in_sizes[0] / D1;     // 500000
    int N = in_sizes[2];          // 100000 (node_batch element count)
    float* out = (float*)d_out;

    const int SMEM1 = (8192 + 16384 + 8192 + 256) * 4;   // 132096
    const int SMEM2 = (8192 + 8192 + 4096 + 256) * 4;    // 82944
    cudaFuncSetAttribute(k_mlp1_scatter, cudaFuncAttributeMaxDynamicSharedMemorySize, SMEM1);
    cudaFuncSetAttribute(k_mlp2,         cudaFuncAttributeMaxDynamicSharedMemorySize, SMEM2);

    int n4 = (N * D1) / 4;
    k_zero<<<(n4 + 255) / 256, 256>>>(n4);

    k_mlp1_scatter<<<(T + TM - 1) / TM, 256, SMEM1>>>(
        x, tok, op_g, op_b, op_m, op_v, op_w1, op_b1, op_w2, op_b2, T);

    k_mlp2<<<(N + TM - 1) / TM, 256, SMEM2>>>(
        nm_g, nm_b, nm_m, nm_v, nm_w1, nm_b1, nm_w2, nm_b2, out, N);
}

// round 6
// speedup vs baseline: 5.1671x; 5.1671x over previous
#include <cuda_runtime.h>
#include <cuda_bf16.h>
#include <cstdint>

typedef unsigned int u32;
typedef unsigned long long u64;

#define NMAX 100000

// ---------------- persistent scratch (plain row-major) ----------------
__device__ float g_nf[NMAX * 128];
__device__ __align__(16) __nv_bfloat16 g_w1hi[256 * 128];   // BN-folded
__device__ __align__(16) __nv_bfloat16 g_w1lo[256 * 128];
__device__ __align__(16) __nv_bfloat16 g_w2hi[256 * 256];
__device__ __align__(16) __nv_bfloat16 g_w2lo[256 * 256];
__device__ __align__(16) __nv_bfloat16 g_nw1hi[128 * 128];  // BN-folded
__device__ __align__(16) __nv_bfloat16 g_nw1lo[128 * 128];
__device__ __align__(16) __nv_bfloat16 g_nw2hi[128 * 128];
__device__ __align__(16) __nv_bfloat16 g_nw2lo[128 * 128];
__device__ float g_b1f[256];
__device__ float g_nb1f[128];

// ---------------- helpers ----------------
__device__ __forceinline__ u32 s2u(const void* p) {
    u32 a;
    asm("{ .reg .u64 t; cvta.to.shared.u64 t, %1; cvt.u32.u64 %0, t; }" : "=r"(a) : "l"(p));
    return a;
}
__device__ __forceinline__ void ldsm4(u32 a, u32& r0, u32& r1, u32& r2, u32& r3) {
    asm volatile("ldmatrix.sync.aligned.m8n8.x4.shared.b16 {%0,%1,%2,%3}, [%4];"
                 : "=r"(r0), "=r"(r1), "=r"(r2), "=r"(r3) : "r"(a));
}
__device__ __forceinline__ void sts32(u32 a, u32 v) {
    asm volatile("st.shared.b32 [%0], %1;" :: "r"(a), "r"(v));
}
__device__ __forceinline__ void sts64(u32 a, u32 x, u32 y) {
    asm volatile("st.shared.v2.b32 [%0], {%1,%2};" :: "r"(a), "r"(x), "r"(y));
}
__device__ __forceinline__ void cpa16(u32 dst, const void* src) {
    asm volatile("cp.async.cg.shared.global [%0], [%1], 16;" :: "r"(dst), "l"(src));
}
#define CP_COMMIT() asm volatile("cp.async.commit_group;")
#define CP_WAIT0()  asm volatile("cp.async.wait_group 0;")

__device__ __forceinline__ void mma16816(float* d, const u32* a, u32 b0, u32 b1) {
    asm volatile(
        "mma.sync.aligned.m16n8k16.row.col.f32.bf16.bf16.f32 "
        "{%0,%1,%2,%3}, {%4,%5,%6,%7}, {%8,%9}, {%0,%1,%2,%3};"
        : "+f"(d[0]), "+f"(d[1]), "+f"(d[2]), "+f"(d[3])
        : "r"(a[0]), "r"(a[1]), "r"(a[2]), "r"(a[3]), "r"(b0), "r"(b1));
}
__device__ __forceinline__ void red2(float* p, float a, float b) {
    asm volatile("red.global.add.v2.f32 [%0], {%1,%2};" :: "l"(p), "f"(a), "f"(b) : "memory");
}
__device__ __forceinline__ u32 pack2bf(__nv_bfloat16 a, __nv_bfloat16 b) {
    return (u32)__bfloat16_as_ushort(a) | ((u32)__bfloat16_as_ushort(b) << 16);
}
__device__ __forceinline__ void split1(float v, __nv_bfloat16& h, __nv_bfloat16& l) {
    h = __float2bfloat16(v);
    l = __float2bfloat16(v - __bfloat162float(h));
}
__device__ __forceinline__ void splitpack(float f0, float f1, u32& hi, u32& lo) {
    __nv_bfloat16 h0, l0, h1, l1;
    split1(f0, h0, l0); split1(f1, h1, l1);
    hi = pack2bf(h0, h1); lo = pack2bf(l0, l1);
}

// ---------------- prep ----------------
__global__ void k_zero(int n4) {
    int i = blockIdx.x * blockDim.x + threadIdx.x;
    if (i < n4) reinterpret_cast<float4*>(g_nf)[i] = make_float4(0.f, 0.f, 0.f, 0.f);
}
__global__ void k_prep_w1(const float* __restrict__ W, const float* __restrict__ g,
                          const float* __restrict__ v) {
    int i = blockIdx.x * 256 + threadIdx.x;
    if (i >= 256 * 128) return;
    int k = i & 127;
    float w = W[i] * (g[k] * rsqrtf(v[k] + 1e-5f));
    __nv_bfloat16 h, l; split1(w, h, l);
    g_w1hi[i] = h; g_w1lo[i] = l;
}
__global__ void k_prep_w2(const float* __restrict__ W) {
    int i = blockIdx.x * 256 + threadIdx.x;
    if (i >= 256 * 256) return;
    __nv_bfloat16 h, l; split1(W[i], h, l);
    g_w2hi[i] = h; g_w2lo[i] = l;
}
__global__ void k_prep_nw1(const float* __restrict__ W, const float* __restrict__ g,
                           const float* __restrict__ v) {
    int i = blockIdx.x * 256 + threadIdx.x;
    if (i >= 128 * 128) return;
    int k = i & 127;
    float w = W[i] * (g[k] * rsqrtf(v[k] + 1e-5f));
    __nv_bfloat16 h, l; split1(w, h, l);
    g_nw1hi[i] = h; g_nw1lo[i] = l;
}
__global__ void k_prep_nw2(const float* __restrict__ W) {
    int i = blockIdx.x * 256 + threadIdx.x;
    if (i >= 128 * 128) return;
    __nv_bfloat16 h, l; split1(W[i], h, l);
    g_nw2hi[i] = h; g_nw2lo[i] = l;
}
__global__ void k_prep_b1(const float* __restrict__ W, const float* __restrict__ bias,
                          const float* __restrict__ g, const float* __restrict__ b,
                          const float* __restrict__ m, const float* __restrict__ v) {
    int n = blockIdx.x, lane = threadIdx.x;
    float s = 0.f;
    for (int k = lane; k < 128; k += 32) {
        float sc = g[k] * rsqrtf(v[k] + 1e-5f);
        s += W[n * 128 + k] * (b[k] - m[k] * sc);
    }
    for (int o = 16; o; o >>= 1) s += __shfl_xor_sync(~0u, s, o);
    if (lane == 0) g_b1f[n] = bias[n] + s;
}
__global__ void k_prep_nb1(const float* __restrict__ W, const float* __restrict__ bias,
                           const float* __restrict__ g, const float* __restrict__ b,
                           const float* __restrict__ m, const float* __restrict__ v) {
    int n = blockIdx.x, lane = threadIdx.x;
    float s = 0.f;
    for (int k = lane; k < 128; k += 32) {
        float sc = g[k] * rsqrtf(v[k] + 1e-5f);
        s += W[n * 128 + k] * (b[k] - m[k] * sc);
    }
    for (int o = 16; o; o >>= 1) s += __shfl_xor_sync(~0u, s, o);
    if (lane == 0) g_nb1f[n] = bias[n] + s;
}

// ---------------------------------------------------------------------------
// Kernel 1: MLP1 + scatter. 128 tokens/CTA, 512 threads (16 warps, 4x4 grid),
// warp tile 32x64. ldmatrix fragments, swizzle key = (row&7)<<4.
// ---------------------------------------------------------------------------
#define K1_XAH   0u
#define K1_XAL   32768u
#define K1_W1H   65536u
#define K1_W1L   131072u
// after GEMM1: A2H=0 (65536), A2L=65536 (65536); W2 slabs over W1L:
#define K1_BUF0H 131072u
#define K1_BUF0L 147456u
#define K1_BUF1H 163840u
#define K1_BUF1L 180224u
#define K1_B1    196608u
#define K1_B2    197632u
#define K1_SMEM  198656u

__global__ void __launch_bounds__(512, 1) k_mlp1(
    const float* __restrict__ x, const int* __restrict__ tok,
    const float* __restrict__ b2g, int T)
{
    extern __shared__ char sm[];
    const u32 sb = s2u(sm);
    const int tid = threadIdx.x, wid = tid >> 5, l = tid & 31;
    const int lr8 = l & 7;
    const int g = l >> 2, q = l & 3;                 // fragment ownership
    const int wm = (wid & 3) * 32, wn = (wid >> 2) * 64;
    const int t0 = blockIdx.x * 128;
    const u32 keyX = (u32)lr8 << 4;
    const u32 aCX = (u32)((l >> 4) & 1) * 16;        // A: matrices 2,3 = k+8
    const u32 bCX = (u32)((l >> 3) & 1) * 16;        // B: matrices 1,3 = k+8

    if (tid < 256) {
        ((float*)(sm + K1_B1))[tid] = g_b1f[tid];
        ((float*)(sm + K1_B2))[tid] = b2g[tid];
    }

    // W1 hi/lo resident: 256 rows x 256B each
    #pragma unroll
    for (int i = 0; i < 8; ++i) {
        int idx = tid + i * 512;                     // 0..4095
        int n = idx >> 4, seg = idx & 15;
        u32 o = (u32)n * 256 + (u32)seg * 16;
        u32 ph = o ^ (((u32)(n & 7)) << 4);
        cpa16(sb + K1_W1H + ph, (const char*)g_w1hi + o);
        cpa16(sb + K1_W1L + ph, (const char*)g_w1lo + o);
    }
    CP_COMMIT();

    // x tile [128,128] -> split hi/lo (row-major bf16, swizzled)
    #pragma unroll
    for (int i = 0; i < 8; ++i) {
        int idx = tid + i * 512;                     // float4 0..4095
        int r = idx >> 5, c = (idx & 31) * 4;        // col (floats)
        float4 v = make_float4(0.f, 0.f, 0.f, 0.f);
        if (t0 + r < T) v = *reinterpret_cast<const float4*>(x + (size_t)(t0 + r) * 128 + c);
        u32 h01, l01, h23, l23;
        splitpack(v.x, v.y, h01, l01);
        splitpack(v.z, v.w, h23, l23);
        u32 o = (u32)r * 256 + (((u32)c * 2) ^ (((u32)(r & 7)) << 4));
        sts64(sb + K1_XAH + o, h01, h23);
        sts64(sb + K1_XAL + o, l01, l23);
    }
    CP_WAIT0();
    __syncthreads();

    // ---------------- GEMM1: y1 = x @ W1^T ----------------
    float acc[2][8][4];
    #pragma unroll
    for (int mt = 0; mt < 2; ++mt)
        #pragma unroll
        for (int nt = 0; nt < 8; ++nt)
            #pragma unroll
            for (int j = 0; j < 4; ++j) acc[mt][nt][j] = 0.f;

    {
        const u32 PA = K1_XAH + (u32)(wm + lr8 + ((l >> 3) & 1) * 8) * 256u + keyX;
        const u32 PB = K1_W1H + (u32)(wn + lr8 + ((l >> 4) & 1) * 8) * 256u + keyX;
        #pragma unroll
        for (int kt = 0; kt < 8; ++kt) {
            u32 ca = (u32)kt * 32 + aCX, cb = (u32)kt * 32 + bCX;
            u32 Ah[2][4], Al[2][4];
            ldsm4(sb + ((PA)          ^ ca), Ah[0][0], Ah[0][1], Ah[0][2], Ah[0][3]);
            ldsm4(sb + ((PA + 4096u)  ^ ca), Ah[1][0], Ah[1][1], Ah[1][2], Ah[1][3]);
            ldsm4(sb + ((PA + 32768u) ^ ca), Al[0][0], Al[0][1], Al[0][2], Al[0][3]);
            ldsm4(sb + ((PA + 36864u) ^ ca), Al[1][0], Al[1][1], Al[1][2], Al[1][3]);
            #pragma unroll
            for (int ntg = 0; ntg < 4; ++ntg) {
                u32 bh[4], bl[4];
                ldsm4(sb + ((PB + (u32)ntg * 4096u) ^ cb), bh[0], bh[1], bh[2], bh[3]);
                ldsm4(sb + ((PB + 65536u + (u32)ntg * 4096u) ^ cb), bl[0], bl[1], bl[2], bl[3]);
                #pragma unroll
                for (int sub = 0; sub < 2; ++sub) {
                    int nt = ntg * 2 + sub;
                    #pragma unroll
                    for (int mt = 0; mt < 2; ++mt) {
                        mma16816(acc[mt][nt], Ah[mt], bh[sub * 2], bh[sub * 2 + 1]);
                        mma16816(acc[mt][nt], Ah[mt], bl[sub * 2], bl[sub * 2 + 1]);
                        mma16816(acc[mt][nt], Al[mt], bh[sub * 2], bh[sub * 2 + 1]);
                    }
                }
            }
        }
    }
    __syncthreads();   // all GEMM1 reads done; regions may be reused

    // prefetch W2 slab 0 (k 0..31) into buf0
    #pragma unroll
    for (int i = 0; i < 2; ++i) {
        int idx = tid + i * 512;                     // 0..1023
        int n = idx >> 2, seg = idx & 3;
        u32 o = (u32)n * 64 + (u32)seg * 16;
        u32 ph = o ^ (((u32)(n & 7)) << 4);
        size_t src = (size_t)n * 512 + (size_t)seg * 16;
        cpa16(sb + K1_BUF0H + ph, (const char*)g_w2hi + src);
        cpa16(sb + K1_BUF0L + ph, (const char*)g_w2lo + src);
    }
    CP_COMMIT();

    // epilogue1: A2 = split(relu(y1 + b1f)), 128 rows x 256 bf16 (512B stride)
    {
        const float* b1s = (const float*)(sm + K1_B1);
        const u32 kr = (u32)g << 4;
        #pragma unroll
        for (int mt = 0; mt < 2; ++mt) {
            u32 row = (u32)(wm + mt * 16 + g);
            #pragma unroll
            for (int nt = 0; nt < 8; ++nt) {
                int c0 = wn + nt * 8 + q * 2;
                float bx = b1s[c0], by = b1s[c0 + 1];
                float f0 = fmaxf(acc[mt][nt][0] + bx, 0.f);
                float f1 = fmaxf(acc[mt][nt][1] + by, 0.f);
                float f2 = fmaxf(acc[mt][nt][2] + bx, 0.f);
                float f3 = fmaxf(acc[mt][nt][3] + by, 0.f);
                u32 col = ((u32)c0 * 2) ^ kr;
                u32 oA = row * 512 + col;
                u32 oB = (row + 8) * 512 + col;
                u32 hi, lo;
                splitpack(f0, f1, hi, lo);
                sts32(sb + oA, hi); sts32(sb + 65536u + oA, lo);
                splitpack(f2, f3, hi, lo);
                sts32(sb + oB, hi); sts32(sb + 65536u + oB, lo);
            }
        }
    }
    CP_WAIT0();
    __syncthreads();

    // ---------------- GEMM2: y2 = relu(y1) @ W2^T (K=256, 8 slabs of 32) ----
    #pragma unroll
    for (int mt = 0; mt < 2; ++mt)
        #pragma unroll
        for (int nt = 0; nt < 8; ++nt)
            #pragma unroll
            for (int j = 0; j < 4; ++j) acc[mt][nt][j] = 0.f;

    {
        const u32 PA2 = (u32)(wm + lr8 + ((l >> 3) & 1) * 8) * 512u + keyX;   // A2H=0
        const u32 PW2 = ((u32)(wn + lr8 + ((l >> 4) & 1) * 8) * 64u) ^ keyX;
        #pragma unroll 1
        for (int s = 0; s < 8; ++s) {
            if (s < 7) {
                u32 dH = (s & 1) ? K1_BUF0H : K1_BUF1H;   // next slab -> other buffer
                u32 dL = (s & 1) ? K1_BUF0L : K1_BUF1L;
                #pragma unroll
                for (int i = 0; i < 2; ++i) {
                    int idx = tid + i * 512;
                    int n = idx >> 2, seg = idx & 3;
                    u32 o = (u32)n * 64 + (u32)seg * 16;
                    u32 ph = o ^ (((u32)(n & 7)) << 4);
                    size_t src = (size_t)n * 512 + (size_t)(s + 1) * 64 + (size_t)seg * 16;
                    cpa16(sb + dH + ph, (const char*)g_w2hi + src);
                    cpa16(sb + dL + ph, (const char*)g_w2lo + src);
                }
                CP_COMMIT();
            }
            u32 bH = (s & 1) ? K1_BUF1H : K1_BUF0H;
            u32 bL = (s & 1) ? K1_BUF1L : K1_BUF0L;
            #pragma unroll
            for (int ktL = 0; ktL < 2; ++ktL) {
                int kt = s * 2 + ktL;
                u32 ca = (u32)kt * 32 + aCX;
                u32 cw = (u32)ktL * 32 + bCX;
                u32 Ah[2][4], Al[2][4];
                ldsm4(sb + ((PA2)           ^ ca), Ah[0][0], Ah[0][1], Ah[0][2], Ah[0][3]);
                ldsm4(sb + ((PA2 + 8192u)   ^ ca), Ah[1][0], Ah[1][1], Ah[1][2], Ah[1][3]);
                ldsm4(sb + ((PA2 + 65536u)  ^ ca), Al[0][0], Al[0][1], Al[0][2], Al[0][3]);
                ldsm4(sb + ((PA2 + 73728u)  ^ ca), Al[1][0], Al[1][1], Al[1][2], Al[1][3]);
                #pragma unroll
                for (int ntg = 0; ntg < 4; ++ntg) {
                    u32 bh[4], bl[4];
                    ldsm4(sb + bH + ((PW2 + (u32)ntg * 1024u) ^ cw), bh[0], bh[1], bh[2], bh[3]);
                    ldsm4(sb + bL + ((PW2 + (u32)ntg * 1024u) ^ cw), bl[0], bl[1], bl[2], bl[3]);
                    #pragma unroll
                    for (int sub = 0; sub < 2; ++sub) {
                        int nt = ntg * 2 + sub;
                        #pragma unroll
                        for (int mt = 0; mt < 2; ++mt) {
                            mma16816(acc[mt][nt], Ah[mt], bh[sub * 2], bh[sub * 2 + 1]);
                            mma16816(acc[mt][nt], Ah[mt], bl[sub * 2], bl[sub * 2 + 1]);
                            mma16816(acc[mt][nt], Al[mt], bh[sub * 2], bh[sub * 2 + 1]);
                        }
                    }
                }
            }
            if (s < 7) CP_WAIT0();
            __syncthreads();
        }
    }

    // ---------------- scatter: cols 0..127 -> tok[0], 128..255 -> tok[1] ----
    {
        const float* b2s = (const float*)(sm + K1_B2);
        int cofs = (wn < 128) ? 0 : 128;
        #pragma unroll
        for (int mt = 0; mt < 2; ++mt) {
            int tA = t0 + wm + mt * 16 + g;
            int tB = tA + 8;
            float* rowA = nullptr; float* rowB = nullptr;
            if (tA < T) {
                int nd = (cofs == 0) ? tok[tA] : tok[T + tA];
                rowA = g_nf + (size_t)nd * 128;
            }
            if (tB < T) {
                int nd = (cofs == 0) ? tok[tB] : tok[T + tB];
                rowB = g_nf + (size_t)nd * 128;
            }
            #pragma unroll
            for (int nt = 0; nt < 8; ++nt) {
                int c0 = wn + nt * 8 + q * 2;
                float bx = b2s[c0], by = b2s[c0 + 1];
                int cl = c0 - cofs;
                if (rowA) red2(rowA + cl, acc[mt][nt][0] + bx, acc[mt][nt][1] + by);
                if (rowB) red2(rowB + cl, acc[mt][nt][2] + bx, acc[mt][nt][3] + by);
            }
        }
    }
}

// ---------------------------------------------------------------------------
// Kernel 2: MLP2. 128 nodes/CTA, 512 threads, warp tile 32x32.
// ---------------------------------------------------------------------------
#define K2_XAH  0u
#define K2_XAL  32768u
#define K2_WH   65536u
#define K2_WL   98304u
#define K2_B1   131072u
#define K2_B2   131584u
#define K2_SMEM 132096u

__global__ void __launch_bounds__(512, 1) k_mlp2(
    const float* __restrict__ b2g, float* __restrict__ out, int NN)
{
    extern __shared__ char sm[];
    const u32 sb = s2u(sm);
    const int tid = threadIdx.x, wid = tid >> 5, l = tid & 31;
    const int lr8 = l & 7;
    const int g = l >> 2, q = l & 3;
    const int wm = (wid & 3) * 32, wn = (wid >> 2) * 32;
    const int n0 = blockIdx.x * 128;
    const u32 keyX = (u32)lr8 << 4;
    const u32 aCX = (u32)((l >> 4) & 1) * 16;
    const u32 bCX = (u32)((l >> 3) & 1) * 16;

    if (tid < 128) {
        ((float*)(sm + K2_B1))[tid] = g_nb1f[tid];
        ((float*)(sm + K2_B2))[tid] = b2g[tid];
    }

    // W1' resident
    #pragma unroll
    for (int i = 0; i < 4; ++i) {
        int idx = tid + i * 512;                      // 0..2047
        int n = idx >> 4, seg = idx & 15;
        u32 o = (u32)n * 256 + (u32)seg * 16;
        u32 ph = o ^ (((u32)(n & 7)) << 4);
        cpa16(sb + K2_WH + ph, (const char*)g_nw1hi + o);
        cpa16(sb + K2_WL + ph, (const char*)g_nw1lo + o);
    }
    CP_COMMIT();

    // nf tile -> split
    #pragma unroll
    for (int i = 0; i < 8; ++i) {
        int idx = tid + i * 512;
        int r = idx >> 5, c = (idx & 31) * 4;
        float4 v = make_float4(0.f, 0.f, 0.f, 0.f);
        if (n0 + r < NN) v = *reinterpret_cast<const float4*>(g_nf + (size_t)(n0 + r) * 128 + c);
        u32 h01, l01, h23, l23;
        splitpack(v.x, v.y, h01, l01);
        splitpack(v.z, v.w, h23, l23);
        u32 o = (u32)r * 256 + (((u32)c * 2) ^ (((u32)(r & 7)) << 4));
        sts64(sb + K2_XAH + o, h01, h23);
        sts64(sb + K2_XAL + o, l01, l23);
    }
    CP_WAIT0();
    __syncthreads();

    float acc[2][4][4];
    const u32 PA = K2_XAH + (u32)(wm + lr8 + ((l >> 3) & 1) * 8) * 256u + keyX;
    const u32 PB = K2_WH  + (u32)(wn + lr8 + ((l >> 4) & 1) * 8) * 256u + keyX;

    // ---- GEMM1 ----
    #pragma unroll
    for (int mt = 0; mt < 2; ++mt)
        #pragma unroll
        for (int nt = 0; nt < 4; ++nt)
            #pragma unroll
            for (int j = 0; j < 4; ++j) acc[mt][nt][j] = 0.f;

    #pragma unroll
    for (int kt = 0; kt < 8; ++kt) {
        u32 ca = (u32)kt * 32 + aCX, cb = (u32)kt * 32 + bCX;
        u32 Ah[2][4], Al[2][4];
        ldsm4(sb + ((PA)          ^ ca), Ah[0][0], Ah[0][1], Ah[0][2], Ah[0][3]);
        ldsm4(sb + ((PA + 4096u)  ^ ca), Ah[1][0], Ah[1][1], Ah[1][2], Ah[1][3]);
        ldsm4(sb + ((PA + 32768u) ^ ca), Al[0][0], Al[0][1], Al[0][2], Al[0][3]);
        ldsm4(sb + ((PA + 36864u) ^ ca), Al[1][0], Al[1][1], Al[1][2], Al[1][3]);
        #pragma unroll
        for (int ntg = 0; ntg < 2; ++ntg) {
            u32 bh[4], bl[4];
            ldsm4(sb + ((PB + (u32)ntg * 4096u) ^ cb), bh[0], bh[1], bh[2], bh[3]);
            ldsm4(sb + ((PB + 32768u + (u32)ntg * 4096u) ^ cb), bl[0], bl[1], bl[2], bl[3]);
            #pragma unroll
            for (int sub = 0; sub < 2; ++sub) {
                int nt = ntg * 2 + sub;
                #pragma unroll
                for (int mt = 0; mt < 2; ++mt) {
                    mma16816(acc[mt][nt], Ah[mt], bh[sub * 2], bh[sub * 2 + 1]);
                    mma16816(acc[mt][nt], Ah[mt], bl[sub * 2], bl[sub * 2 + 1]);
                    mma16816(acc[mt][nt], Al[mt], bh[sub * 2], bh[sub * 2 + 1]);
                }
            }
        }
    }
    __syncthreads();

    // prefetch W2' over W region
    #pragma unroll
    for (int i = 0; i < 4; ++i) {
        int idx = tid + i * 512;
        int n = idx >> 4, seg = idx & 15;
        u32 o = (u32)n * 256 + (u32)seg * 16;
        u32 ph = o ^ (((u32)(n & 7)) << 4);
        cpa16(sb + K2_WH + ph, (const char*)g_nw2hi + o);
        cpa16(sb + K2_WL + ph, (const char*)g_nw2lo + o);
    }
    CP_COMMIT();

    // epilogue1 -> A2 over XA (stride 256)
    {
        const float* b1s = (const float*)(sm + K2_B1);
        const u32 kr = (u32)g << 4;
        #pragma unroll
        for (int mt = 0; mt < 2; ++mt) {
            u32 row = (u32)(wm + mt * 16 + g);
            #pragma unroll
            for (int nt = 0; nt < 4; ++nt) {
                int c0 = wn + nt * 8 + q * 2;
                float bx = b1s[c0], by = b1s[c0 + 1];
                float f0 = fmaxf(acc[mt][nt][0] + bx, 0.f);
                float f1 = fmaxf(acc[mt][nt][1] + by, 0.f);
                float f2 = fmaxf(acc[mt][nt][2] + bx, 0.f);
                float f3 = fmaxf(acc[mt][nt][3] + by, 0.f);
                u32 col = ((u32)c0 * 2) ^ kr;
                u32 oA = row * 256 + col;
                u32 oB = (row + 8) * 256 + col;
                u32 hi, lo;
                splitpack(f0, f1, hi, lo);
                sts32(sb + K2_XAH + oA, hi); sts32(sb + K2_XAL + oA, lo);
                splitpack(f2, f3, hi, lo);
                sts32(sb + K2_XAH + oB, hi); sts32(sb + K2_XAL + oB, lo);
            }
        }
    }
    CP_WAIT0();
    __syncthreads();

    // ---- GEMM2 ----
    #pragma unroll
    for (int mt = 0; mt < 2; ++mt)
        #pragma unroll
        for (int nt = 0; nt < 4; ++nt)
            #pragma unroll
            for (int j = 0; j < 4; ++j) acc[mt][nt][j] = 0.f;

    #pragma unroll
    for (int kt = 0; kt < 8; ++kt) {
        u32 ca = (u32)kt * 32 + aCX, cb = (u32)kt * 32 + bCX;
        u32 Ah[2][4], Al[2][4];
        ldsm4(sb + ((PA)          ^ ca), Ah[0][0], Ah[0][1], Ah[0][2], Ah[0][3]);
        ldsm4(sb + ((PA + 4096u)  ^ ca), Ah[1][0], Ah[1][1], Ah[1][2], Ah[1][3]);
        ldsm4(sb + ((PA + 32768u) ^ ca), Al[0][0], Al[0][1], Al[0][2], Al[0][3]);
        ldsm4(sb + ((PA + 36864u) ^ ca), Al[1][0], Al[1][1], Al[1][2], Al[1][3]);
        #pragma unroll
        for (int ntg = 0; ntg < 2; ++ntg) {
            u32 bh[4], bl[4];
            ldsm4(sb + ((PB + (u32)ntg * 4096u) ^ cb), bh[0], bh[1], bh[2], bh[3]);
            ldsm4(sb + ((PB + 32768u + (u32)ntg * 4096u) ^ cb), bl[0], bl[1], bl[2], bl[3]);
            #pragma unroll
            for (int sub = 0; sub < 2; ++sub) {
                int nt = ntg * 2 + sub;
                #pragma unroll
                for (int mt = 0; mt < 2; ++mt) {
                    mma16816(acc[mt][nt], Ah[mt], bh[sub * 2], bh[sub * 2 + 1]);
                    mma16816(acc[mt][nt], Ah[mt], bl[sub * 2], bl[sub * 2 + 1]);
                    mma16816(acc[mt][nt], Al[mt], bh[sub * 2], bh[sub * 2 + 1]);
                }
            }
        }
    }

    // output
    {
        const float* b2s = (const float*)(sm + K2_B2);
        #pragma unroll
        for (int mt = 0; mt < 2; ++mt) {
            int rA = n0 + wm + mt * 16 + g;
            int rB = rA + 8;
            #pragma unroll
            for (int nt = 0; nt < 4; ++nt) {
                int c0 = wn + nt * 8 + q * 2;
                float bx = b2s[c0], by = b2s[c0 + 1];
                if (rA < NN)
                    *reinterpret_cast<float2*>(out + (size_t)rA * 128 + c0) =
                        make_float2(acc[mt][nt][0] + bx, acc[mt][nt][1] + by);
                if (rB < NN)
                    *reinterpret_cast<float2*>(out + (size_t)rB * 128 + c0) =
                        make_float2(acc[mt][nt][2] + bx, acc[mt][nt][3] + by);
            }
        }
    }
}

// ---------------------------------------------------------------------------
extern "C" void kernel_launch(void* const* d_in, const int* in_sizes, int n_in,
                              void* d_out, int out_size) {
    const float* x    = (const float*)d_in[0];
    const int*   tok  = (const int*)d_in[3];   // int32 (JAX x64 disabled)
    const float* op_g  = (const float*)d_in[4];
    const float* op_b  = (const float*)d_in[5];
    const float* op_m  = (const float*)d_in[6];
    const float* op_v  = (const float*)d_in[7];
    const float* op_w1 = (const float*)d_in[8];
    const float* op_b1 = (const float*)d_in[9];
    const float* op_w2 = (const float*)d_in[10];
    const float* op_b2 = (const float*)d_in[11];
    const float* nm_g  = (const float*)d_in[12];
    const float* nm_b  = (const float*)d_in[13];
    const float* nm_m  = (const float*)d_in[14];
    const float* nm_v  = (const float*)d_in[15];
    const float* nm_w1 = (const float*)d_in[16];
    const float* nm_b1 = (const float*)d_in[17];
    const float* nm_w2 = (const float*)d_in[18];
    const float* nm_b2 = (const float*)d_in[19];

    int T  = in_sizes[0] / 128;
    int NN = in_sizes[2];
    float* out = (float*)d_out;

    cudaFuncSetAttribute(k_mlp1, cudaFuncAttributeMaxDynamicSharedMemorySize, K1_SMEM);
    cudaFuncSetAttribute(k_mlp2, cudaFuncAttributeMaxDynamicSharedMemorySize, K2_SMEM);

    int n4 = (NN * 128) / 4;
    k_zero<<<(n4 + 255) / 256, 256>>>(n4);

    k_prep_w1 <<<(256 * 128 + 255) / 256, 256>>>(op_w1, op_g, op_v);
    k_prep_w2 <<<(256 * 256 + 255) / 256, 256>>>(op_w2);
    k_prep_nw1<<<(128 * 128 + 255) / 256, 256>>>(nm_w1, nm_g, nm_v);
    k_prep_nw2<<<(128 * 128 + 255) / 256, 256>>>(nm_w2);
    k_prep_b1 <<<256, 32>>>(op_w1, op_b1, op_g, op_b, op_m, op_v);
    k_prep_nb1<<<128, 32>>>(nm_w1, nm_b1, nm_g, nm_b, nm_m, nm_v);

    k_mlp1<<<(T + 127) / 128, 512, K1_SMEM>>>(x, tok, op_b2, T);
    k_mlp2<<<(NN + 127) / 128, 512, K2_SMEM>>>(nm_b2, out, NN);
}

// round 7
// speedup vs baseline: 6.8027x; 1.3165x over previous
#include <cuda_runtime.h>
#include <cuda_fp16.h>
#include <cstdint>

typedef unsigned int u32;
typedef unsigned long long u64;

#define NMAX 100000

// ---------------- persistent scratch ----------------
__device__ float g_nf[NMAX * 128];
__device__ __align__(16) __half g_w1h[256 * 128];    // BN-folded, fp16 RN
__device__ __align__(16) __half g_w2h[256 * 256];
__device__ __align__(16) __half g_nw1h[128 * 128];   // BN-folded
__device__ __align__(16) __half g_nw2h[128 * 128];
__device__ float g_b1f[256];
__device__ float g_nb1f[128];

// ---------------- helpers ----------------
__device__ __forceinline__ u32 s2u(const void* p) {
    u32 a;
    asm("{ .reg .u64 t; cvta.to.shared.u64 t, %1; cvt.u32.u64 %0, t; }" : "=r"(a) : "l"(p));
    return a;
}
__device__ __forceinline__ void ldsm4(u32 a, u32& r0, u32& r1, u32& r2, u32& r3) {
    asm volatile("ldmatrix.sync.aligned.m8n8.x4.shared.b16 {%0,%1,%2,%3}, [%4];"
                 : "=r"(r0), "=r"(r1), "=r"(r2), "=r"(r3) : "r"(a));
}
__device__ __forceinline__ void sts32(u32 a, u32 v) {
    asm volatile("st.shared.b32 [%0], %1;" :: "r"(a), "r"(v));
}
__device__ __forceinline__ void sts64(u32 a, u32 x, u32 y) {
    asm volatile("st.shared.v2.b32 [%0], {%1,%2};" :: "r"(a), "r"(x), "r"(y));
}
__device__ __forceinline__ void cpa16(u32 dst, const void* src) {
    asm volatile("cp.async.cg.shared.global [%0], [%1], 16;" :: "r"(dst), "l"(src));
}
#define CP_COMMIT() asm volatile("cp.async.commit_group;")
#define CP_WAIT0()  asm volatile("cp.async.wait_group 0;")

__device__ __forceinline__ void mma16816(float* d, const u32* a, u32 b0, u32 b1) {
    asm volatile(
        "mma.sync.aligned.m16n8k16.row.col.f32.f16.f16.f32 "
        "{%0,%1,%2,%3}, {%4,%5,%6,%7}, {%8,%9}, {%0,%1,%2,%3};"
        : "+f"(d[0]), "+f"(d[1]), "+f"(d[2]), "+f"(d[3])
        : "r"(a[0]), "r"(a[1]), "r"(a[2]), "r"(a[3]), "r"(b0), "r"(b1));
}
__device__ __forceinline__ void red2(float* p, float a, float b) {
    asm volatile("red.global.add.v2.f32 [%0], {%1,%2};" :: "l"(p), "f"(a), "f"(b) : "memory");
}
__device__ __forceinline__ u32 pack2h(__half a, __half b) {
    return (u32)__half_as_ushort(a) | ((u32)__half_as_ushort(b) << 16);
}
// split float pair into packed fp16 hi / lo
__device__ __forceinline__ void splitpackh(float f0, float f1, u32& hi, u32& lo) {
    __half h0 = __float2half_rn(f0);
    __half h1 = __float2half_rn(f1);
    __half l0 = __float2half_rn(f0 - __half2float(h0));
    __half l1 = __float2half_rn(f1 - __half2float(h1));
    hi = pack2h(h0, h1); lo = pack2h(l0, l1);
}

// ---------------- prep ----------------
__global__ void k_zero(int n4) {
    int i = blockIdx.x * blockDim.x + threadIdx.x;
    if (i < n4) reinterpret_cast<float4*>(g_nf)[i] = make_float4(0.f, 0.f, 0.f, 0.f);
}
// all weight conversions in one kernel: [w1 | w2 | nw1 | nw2]
__global__ void k_prep_w(const float* __restrict__ W1, const float* __restrict__ og,
                         const float* __restrict__ ov, const float* __restrict__ W2,
                         const float* __restrict__ NW1, const float* __restrict__ ng,
                         const float* __restrict__ nv, const float* __restrict__ NW2) {
    int i = blockIdx.x * 256 + threadIdx.x;
    if (i < 32768) {                       // w1 (BN-folded)
        int k = i & 127;
        g_w1h[i] = __float2half_rn(W1[i] * (og[k] * rsqrtf(ov[k] + 1e-5f)));
    } else if (i < 98304) {                // w2
        int j = i - 32768;
        g_w2h[j] = __float2half_rn(W2[j]);
    } else if (i < 114688) {               // nw1 (BN-folded)
        int j = i - 98304;
        int k = j & 127;
        g_nw1h[j] = __float2half_rn(NW1[j] * (ng[k] * rsqrtf(nv[k] + 1e-5f)));
    } else if (i < 131072) {               // nw2
        int j = i - 114688;
        g_nw2h[j] = __float2half_rn(NW2[j]);
    }
}
__global__ void k_prep_b1(const float* __restrict__ W, const float* __restrict__ bias,
                          const float* __restrict__ g, const float* __restrict__ b,
                          const float* __restrict__ m, const float* __restrict__ v) {
    int n = blockIdx.x, lane = threadIdx.x;
    float s = 0.f;
    for (int k = lane; k < 128; k += 32) {
        float sc = g[k] * rsqrtf(v[k] + 1e-5f);
        s += W[n * 128 + k] * (b[k] - m[k] * sc);
    }
    for (int o = 16; o; o >>= 1) s += __shfl_xor_sync(~0u, s, o);
    if (lane == 0) g_b1f[n] = bias[n] + s;
}
__global__ void k_prep_nb1(const float* __restrict__ W, const float* __restrict__ bias,
                           const float* __restrict__ g, const float* __restrict__ b,
                           const float* __restrict__ m, const float* __restrict__ v) {
    int n = blockIdx.x, lane = threadIdx.x;
    float s = 0.f;
    for (int k = lane; k < 128; k += 32) {
        float sc = g[k] * rsqrtf(v[k] + 1e-5f);
        s += W[n * 128 + k] * (b[k] - m[k] * sc);
    }
    for (int o = 16; o; o >>= 1) s += __shfl_xor_sync(~0u, s, o);
    if (lane == 0) g_nb1f[n] = bias[n] + s;
}

// ---------------------------------------------------------------------------
// Kernel 1: MLP1 + scatter. 128 tokens/CTA, 512 threads, warp tile 32x64.
// fp16 2-term: D = ah*wh + al*wh (a-side exact, error = a*wl ~ 2^-12).
// SMEM phase1: XAH 0(32K) XAL 32K W1H 64K(64K)
// SMEM phase2: A2H 0(64K) A2L 64K(64K) W2BUF0 128K(32K) W2BUF1 160K(32K)
// ---------------------------------------------------------------------------
#define K1_XAH   0u
#define K1_XAL   32768u
#define K1_W1H   65536u
#define K1_A2H   0u
#define K1_A2L   65536u
#define K1_BUF0  131072u
#define K1_BUF1  163840u
#define K1_B1    196608u
#define K1_B2    197632u
#define K1_SMEM  198656u

__global__ void __launch_bounds__(512, 1) k_mlp1(
    const float* __restrict__ x, const int* __restrict__ tok,
    const float* __restrict__ b2g, int T)
{
    extern __shared__ char sm[];
    const u32 sb = s2u(sm);
    const int tid = threadIdx.x, wid = tid >> 5, l = tid & 31;
    const int lr8 = l & 7;
    const int g = l >> 2, q = l & 3;
    const int wm = (wid & 3) * 32, wn = (wid >> 2) * 64;
    const int t0 = blockIdx.x * 128;
    const u32 keyX = (u32)lr8 << 4;
    const u32 aCX = (u32)((l >> 4) & 1) * 16;
    const u32 bCX = (u32)((l >> 3) & 1) * 16;

    if (tid < 256) {
        ((float*)(sm + K1_B1))[tid] = g_b1f[tid];
        ((float*)(sm + K1_B2))[tid] = b2g[tid];
    }

    // W1 resident (fp16, 256 rows x 256B)
    #pragma unroll
    for (int i = 0; i < 8; ++i) {
        int idx = tid + i * 512;                     // 0..4095
        int n = idx >> 4, seg = idx & 15;
        u32 o = (u32)n * 256 + (u32)seg * 16;
        cpa16(sb + K1_W1H + (o ^ (((u32)(n & 7)) << 4)), (const char*)g_w1h + o);
    }
    CP_COMMIT();

    // x tile [128,128] -> split fp16 hi/lo
    #pragma unroll
    for (int i = 0; i < 8; ++i) {
        int idx = tid + i * 512;
        int r = idx >> 5, c = (idx & 31) * 4;
        float4 v = make_float4(0.f, 0.f, 0.f, 0.f);
        if (t0 + r < T) v = *reinterpret_cast<const float4*>(x + (size_t)(t0 + r) * 128 + c);
        u32 h01, l01, h23, l23;
        splitpackh(v.x, v.y, h01, l01);
        splitpackh(v.z, v.w, h23, l23);
        u32 o = (u32)r * 256 + (((u32)c * 2) ^ (((u32)(r & 7)) << 4));
        sts64(sb + K1_XAH + o, h01, h23);
        sts64(sb + K1_XAL + o, l01, l23);
    }
    CP_WAIT0();
    __syncthreads();

    // ---------------- GEMM1: y1 = x @ W1^T ----------------
    float acc[2][8][4];
    #pragma unroll
    for (int mt = 0; mt < 2; ++mt)
        #pragma unroll
        for (int nt = 0; nt < 8; ++nt)
            #pragma unroll
            for (int j = 0; j < 4; ++j) acc[mt][nt][j] = 0.f;

    {
        const u32 PA = K1_XAH + (u32)(wm + lr8 + ((l >> 3) & 1) * 8) * 256u + keyX;
        const u32 PB = K1_W1H + (u32)(wn + lr8 + ((l >> 4) & 1) * 8) * 256u + keyX;
        #pragma unroll
        for (int kt = 0; kt < 8; ++kt) {
            u32 ca = (u32)kt * 32 + aCX, cb = (u32)kt * 32 + bCX;
            u32 Ah[2][4], Al[2][4];
            ldsm4(sb + ((PA)          ^ ca), Ah[0][0], Ah[0][1], Ah[0][2], Ah[0][3]);
            ldsm4(sb + ((PA + 4096u)  ^ ca), Ah[1][0], Ah[1][1], Ah[1][2], Ah[1][3]);
            ldsm4(sb + ((PA + 32768u) ^ ca), Al[0][0], Al[0][1], Al[0][2], Al[0][3]);
            ldsm4(sb + ((PA + 36864u) ^ ca), Al[1][0], Al[1][1], Al[1][2], Al[1][3]);
            #pragma unroll
            for (int ntg = 0; ntg < 4; ++ntg) {
                u32 bh[4];
                ldsm4(sb + ((PB + (u32)ntg * 4096u) ^ cb), bh[0], bh[1], bh[2], bh[3]);
                #pragma unroll
                for (int sub = 0; sub < 2; ++sub) {
                    int nt = ntg * 2 + sub;
                    #pragma unroll
                    for (int mt = 0; mt < 2; ++mt) {
                        mma16816(acc[mt][nt], Ah[mt], bh[sub * 2], bh[sub * 2 + 1]);
                        mma16816(acc[mt][nt], Al[mt], bh[sub * 2], bh[sub * 2 + 1]);
                    }
                }
            }
        }
    }
    __syncthreads();   // GEMM1 reads done; XA/W1H regions reusable

    // prefetch W2 slab 0 (k 0..63): 256 rows x 128B
    #pragma unroll
    for (int i = 0; i < 4; ++i) {
        int idx = tid + i * 512;                     // 0..2047
        int n = idx >> 3, seg = idx & 7;
        u32 o = (u32)n * 128 + (u32)seg * 16;
        cpa16(sb + K1_BUF0 + (o ^ (((u32)(n & 7)) << 4)),
              (const char*)g_w2h + (size_t)n * 512 + (size_t)seg * 16);
    }
    CP_COMMIT();

    // epilogue1: A2 = split_fp16(relu(y1 + b1f)), 128 rows x 512B
    {
        const float* b1s = (const float*)(sm + K1_B1);
        const u32 kr = (u32)g << 4;
        #pragma unroll
        for (int mt = 0; mt < 2; ++mt) {
            u32 row = (u32)(wm + mt * 16 + g);
            #pragma unroll
            for (int nt = 0; nt < 8; ++nt) {
                int c0 = wn + nt * 8 + q * 2;
                float bx = b1s[c0], by = b1s[c0 + 1];
                float f0 = fmaxf(acc[mt][nt][0] + bx, 0.f);
                float f1 = fmaxf(acc[mt][nt][1] + by, 0.f);
                float f2 = fmaxf(acc[mt][nt][2] + bx, 0.f);
                float f3 = fmaxf(acc[mt][nt][3] + by, 0.f);
                u32 col = ((u32)c0 * 2) ^ kr;
                u32 oA = row * 512 + col;
                u32 oB = (row + 8) * 512 + col;
                u32 hi, lo;
                splitpackh(f0, f1, hi, lo);
                sts32(sb + K1_A2H + oA, hi); sts32(sb + K1_A2L + oA, lo);
                splitpackh(f2, f3, hi, lo);
                sts32(sb + K1_A2H + oB, hi); sts32(sb + K1_A2L + oB, lo);
            }
        }
    }
    CP_WAIT0();
    __syncthreads();

    // ---------------- GEMM2: y2 = relu(y1) @ W2^T (K=256, 4 slabs of 64) ----
    #pragma unroll
    for (int mt = 0; mt < 2; ++mt)
        #pragma unroll
        for (int nt = 0; nt < 8; ++nt)
            #pragma unroll
            for (int j = 0; j < 4; ++j) acc[mt][nt][j] = 0.f;

    {
        const u32 PA2 = K1_A2H + (u32)(wm + lr8 + ((l >> 3) & 1) * 8) * 512u + keyX;
        const u32 PW2 = (u32)(wn + lr8 + ((l >> 4) & 1) * 8) * 128u + keyX;
        #pragma unroll 1
        for (int s = 0; s < 4; ++s) {
            if (s < 3) {
                u32 dB = (s & 1) ? K1_BUF0 : K1_BUF1;
                #pragma unroll
                for (int i = 0; i < 4; ++i) {
                    int idx = tid + i * 512;
                    int n = idx >> 3, seg = idx & 7;
                    u32 o = (u32)n * 128 + (u32)seg * 16;
                    size_t src = (size_t)n * 512 + (size_t)(s + 1) * 128 + (size_t)seg * 16;
                    cpa16(sb + dB + (o ^ (((u32)(n & 7)) << 4)), (const char*)g_w2h + src);
                }
                CP_COMMIT();
            }
            u32 bB = sb + ((s & 1) ? K1_BUF1 : K1_BUF0);
            #pragma unroll
            for (int ktL = 0; ktL < 4; ++ktL) {
                int kt = s * 4 + ktL;
                u32 ca = (u32)kt * 32 + aCX;
                u32 cw = (u32)ktL * 32 + bCX;
                u32 Ah[2][4], Al[2][4];
                ldsm4(sb + ((PA2)          ^ ca), Ah[0][0], Ah[0][1], Ah[0][2], Ah[0][3]);
                ldsm4(sb + ((PA2 + 8192u)  ^ ca), Ah[1][0], Ah[1][1], Ah[1][2], Ah[1][3]);
                ldsm4(sb + ((PA2 + 65536u) ^ ca), Al[0][0], Al[0][1], Al[0][2], Al[0][3]);
                ldsm4(sb + ((PA2 + 73728u) ^ ca), Al[1][0], Al[1][1], Al[1][2], Al[1][3]);
                #pragma unroll
                for (int ntg = 0; ntg < 4; ++ntg) {
                    u32 bh[4];
                    ldsm4(bB + ((PW2 + (u32)ntg * 2048u) ^ cw), bh[0], bh[1], bh[2], bh[3]);
                    #pragma unroll
                    for (int sub = 0; sub < 2; ++sub) {
                        int nt = ntg * 2 + sub;
                        #pragma unroll
                        for (int mt = 0; mt < 2; ++mt) {
                            mma16816(acc[mt][nt], Ah[mt], bh[sub * 2], bh[sub * 2 + 1]);
                            mma16816(acc[mt][nt], Al[mt], bh[sub * 2], bh[sub * 2 + 1]);
                        }
                    }
                }
            }
            if (s < 3) CP_WAIT0();
            __syncthreads();
        }
    }

    // ---------------- scatter ----------------
    {
        const float* b2s = (const float*)(sm + K1_B2);
        int cofs = (wn < 128) ? 0 : 128;
        #pragma unroll
        for (int mt = 0; mt < 2; ++mt) {
            int tA = t0 + wm + mt * 16 + g;
            int tB = tA + 8;
            float* rowA = nullptr; float* rowB = nullptr;
            if (tA < T) {
                int nd = (cofs == 0) ? tok[tA] : tok[T + tA];
                rowA = g_nf + (size_t)nd * 128;
            }
            if (tB < T) {
                int nd = (cofs == 0) ? tok[tB] : tok[T + tB];
                rowB = g_nf + (size_t)nd * 128;
            }
            #pragma unroll
            for (int nt = 0; nt < 8; ++nt) {
                int c0 = wn + nt * 8 + q * 2;
                float bx = b2s[c0], by = b2s[c0 + 1];
                int cl = c0 - cofs;
                if (rowA) red2(rowA + cl, acc[mt][nt][0] + bx, acc[mt][nt][1] + by);
                if (rowB) red2(rowB + cl, acc[mt][nt][2] + bx, acc[mt][nt][3] + by);
            }
        }
    }
}

// ---------------------------------------------------------------------------
// Kernel 2: MLP2. 128 nodes/CTA, 512 threads, warp tile 32x32, fp16 2-term.
// ---------------------------------------------------------------------------
#define K2_XAH  0u
#define K2_XAL  32768u
#define K2_WH   65536u
#define K2_B1   98304u
#define K2_B2   98816u
#define K2_SMEM 99328u

__global__ void __launch_bounds__(512, 1) k_mlp2(
    const float* __restrict__ b2g, float* __restrict__ out, int NN)
{
    extern __shared__ char sm[];
    const u32 sb = s2u(sm);
    const int tid = threadIdx.x, wid = tid >> 5, l = tid & 31;
    const int lr8 = l & 7;
    const int g = l >> 2, q = l & 3;
    const int wm = (wid & 3) * 32, wn = (wid >> 2) * 32;
    const int n0 = blockIdx.x * 128;
    const u32 keyX = (u32)lr8 << 4;
    const u32 aCX = (u32)((l >> 4) & 1) * 16;
    const u32 bCX = (u32)((l >> 3) & 1) * 16;

    if (tid < 128) {
        ((float*)(sm + K2_B1))[tid] = g_nb1f[tid];
        ((float*)(sm + K2_B2))[tid] = b2g[tid];
    }

    // W1' resident (128 rows x 256B)
    #pragma unroll
    for (int i = 0; i < 4; ++i) {
        int idx = tid + i * 512;                      // 0..2047
        int n = idx >> 4, seg = idx & 15;
        u32 o = (u32)n * 256 + (u32)seg * 16;
        cpa16(sb + K2_WH + (o ^ (((u32)(n & 7)) << 4)), (const char*)g_nw1h + o);
    }
    CP_COMMIT();

    // nf tile -> split fp16
    #pragma unroll
    for (int i = 0; i < 8; ++i) {
        int idx = tid + i * 512;
        int r = idx >> 5, c = (idx & 31) * 4;
        float4 v = make_float4(0.f, 0.f, 0.f, 0.f);
        if (n0 + r < NN) v = *reinterpret_cast<const float4*>(g_nf + (size_t)(n0 + r) * 128 + c);
        u32 h01, l01, h23, l23;
        splitpackh(v.x, v.y, h01, l01);
        splitpackh(v.z, v.w, h23, l23);
        u32 o = (u32)r * 256 + (((u32)c * 2) ^ (((u32)(r & 7)) << 4));
        sts64(sb + K2_XAH + o, h01, h23);
        sts64(sb + K2_XAL + o, l01, l23);
    }
    CP_WAIT0();
    __syncthreads();

    float acc[2][4][4];
    const u32 PA = K2_XAH + (u32)(wm + lr8 + ((l >> 3) & 1) * 8) * 256u + keyX;
    const u32 PB = K2_WH  + (u32)(wn + lr8 + ((l >> 4) & 1) * 8) * 256u + keyX;

    // ---- GEMM1 ----
    #pragma unroll
    for (int mt = 0; mt < 2; ++mt)
        #pragma unroll
        for (int nt = 0; nt < 4; ++nt)
            #pragma unroll
            for (int j = 0; j < 4; ++j) acc[mt][nt][j] = 0.f;

    #pragma unroll
    for (int kt = 0; kt < 8; ++kt) {
        u32 ca = (u32)kt * 32 + aCX, cb = (u32)kt * 32 + bCX;
        u32 Ah[2][4], Al[2][4];
        ldsm4(sb + ((PA)          ^ ca), Ah[0][0], Ah[0][1], Ah[0][2], Ah[0][3]);
        ldsm4(sb + ((PA + 4096u)  ^ ca), Ah[1][0], Ah[1][1], Ah[1][2], Ah[1][3]);
        ldsm4(sb + ((PA + 32768u) ^ ca), Al[0][0], Al[0][1], Al[0][2], Al[0][3]);
        ldsm4(sb + ((PA + 36864u) ^ ca), Al[1][0], Al[1][1], Al[1][2], Al[1][3]);
        #pragma unroll
        for (int ntg = 0; ntg < 2; ++ntg) {
            u32 bh[4];
            ldsm4(sb + ((PB + (u32)ntg * 4096u) ^ cb), bh[0], bh[1], bh[2], bh[3]);
            #pragma unroll
            for (int sub = 0; sub < 2; ++sub) {
                int nt = ntg * 2 + sub;
                #pragma unroll
                for (int mt = 0; mt < 2; ++mt) {
                    mma16816(acc[mt][nt], Ah[mt], bh[sub * 2], bh[sub * 2 + 1]);
                    mma16816(acc[mt][nt], Al[mt], bh[sub * 2], bh[sub * 2 + 1]);
                }
            }
        }
    }
    __syncthreads();

    // prefetch W2' over W region
    #pragma unroll
    for (int i = 0; i < 4; ++i) {
        int idx = tid + i * 512;
        int n = idx >> 4, seg = idx & 15;
        u32 o = (u32)n * 256 + (u32)seg * 16;
        cpa16(sb + K2_WH + (o ^ (((u32)(n & 7)) << 4)), (const char*)g_nw2h + o);
    }
    CP_COMMIT();

    // epilogue1 -> A2 over XA (stride 256B)
    {
        const float* b1s = (const float*)(sm + K2_B1);
        const u32 kr = (u32)g << 4;
        #pragma unroll
        for (int mt = 0; mt < 2; ++mt) {
            u32 row = (u32)(wm + mt * 16 + g);
            #pragma unroll
            for (int nt = 0; nt < 4; ++nt) {
                int c0 = wn + nt * 8 + q * 2;
                float bx = b1s[c0], by = b1s[c0 + 1];
                float f0 = fmaxf(acc[mt][nt][0] + bx, 0.f);
                float f1 = fmaxf(acc[mt][nt][1] + by, 0.f);
                float f2 = fmaxf(acc[mt][nt][2] + bx, 0.f);
                float f3 = fmaxf(acc[mt][nt][3] + by, 0.f);
                u32 col = ((u32)c0 * 2) ^ kr;
                u32 oA = row * 256 + col;
                u32 oB = (row + 8) * 256 + col;
                u32 hi, lo;
                splitpackh(f0, f1, hi, lo);
                sts32(sb + K2_XAH + oA, hi); sts32(sb + K2_XAL + oA, lo);
                splitpackh(f2, f3, hi, lo);
                sts32(sb + K2_XAH + oB, hi); sts32(sb + K2_XAL + oB, lo);
            }
        }
    }
    CP_WAIT0();
    __syncthreads();

    // ---- GEMM2 ----
    #pragma unroll
    for (int mt = 0; mt < 2; ++mt)
        #pragma unroll
        for (int nt = 0; nt < 4; ++nt)
            #pragma unroll
            for (int j = 0; j < 4; ++j) acc[mt][nt][j] = 0.f;

    #pragma unroll
    for (int kt = 0; kt < 8; ++kt) {
        u32 ca = (u32)kt * 32 + aCX, cb = (u32)kt * 32 + bCX;
        u32 Ah[2][4], Al[2][4];
        ldsm4(sb + ((PA)          ^ ca), Ah[0][0], Ah[0][1], Ah[0][2], Ah[0][3]);
        ldsm4(sb + ((PA + 4096u)  ^ ca), Ah[1][0], Ah[1][1], Ah[1][2], Ah[1][3]);
        ldsm4(sb + ((PA + 32768u) ^ ca), Al[0][0], Al[0][1], Al[0][2], Al[0][3]);
        ldsm4(sb + ((PA + 36864u) ^ ca), Al[1][0], Al[1][1], Al[1][2], Al[1][3]);
        #pragma unroll
        for (int ntg = 0; ntg < 2; ++ntg) {
            u32 bh[4];
            ldsm4(sb + ((PB + (u32)ntg * 4096u) ^ cb), bh[0], bh[1], bh[2], bh[3]);
            #pragma unroll
            for (int sub = 0; sub < 2; ++sub) {
                int nt = ntg * 2 + sub;
                #pragma unroll
                for (int mt = 0; mt < 2; ++mt) {
                    mma16816(acc[mt][nt], Ah[mt], bh[sub * 2], bh[sub * 2 + 1]);
                    mma16816(acc[mt][nt], Al[mt], bh[sub * 2], bh[sub * 2 + 1]);
                }
            }
        }
    }

    // output
    {
        const float* b2s = (const float*)(sm + K2_B2);
        #pragma unroll
        for (int mt = 0; mt < 2; ++mt) {
            int rA = n0 + wm + mt * 16 + g;
            int rB = rA + 8;
            #pragma unroll
            for (int nt = 0; nt < 4; ++nt) {
                int c0 = wn + nt * 8 + q * 2;
                float bx = b2s[c0], by = b2s[c0 + 1];
                if (rA < NN)
                    *reinterpret_cast<float2*>(out + (size_t)rA * 128 + c0) =
                        make_float2(acc[mt][nt][0] + bx, acc[mt][nt][1] + by);
                if (rB < NN)
                    *reinterpret_cast<float2*>(out + (size_t)rB * 128 + c0) =
                        make_float2(acc[mt][nt][2] + bx, acc[mt][nt][3] + by);
            }
        }
    }
}

// ---------------------------------------------------------------------------
extern "C" void kernel_launch(void* const* d_in, const int* in_sizes, int n_in,
                              void* d_out, int out_size) {
    const float* x    = (const float*)d_in[0];
    const int*   tok  = (const int*)d_in[3];   // int32 (JAX x64 disabled)
    const float* op_g  = (const float*)d_in[4];
    const float* op_b  = (const float*)d_in[5];
    const float* op_m  = (const float*)d_in[6];
    const float* op_v  = (const float*)d_in[7];
    const float* op_w1 = (const float*)d_in[8];
    const float* op_b1 = (const float*)d_in[9];
    const float* op_w2 = (const float*)d_in[10];
    const float* op_b2 = (const float*)d_in[11];
    const float* nm_g  = (const float*)d_in[12];
    const float* nm_b  = (const float*)d_in[13];
    const float* nm_m  = (const float*)d_in[14];
    const float* nm_v  = (const float*)d_in[15];
    const float* nm_w1 = (const float*)d_in[16];
    const float* nm_b1 = (const float*)d_in[17];
    const float* nm_w2 = (const float*)d_in[18];
    const float* nm_b2 = (const float*)d_in[19];

    int T  = in_sizes[0] / 128;
    int NN = in_sizes[2];
    float* out = (float*)d_out;

    cudaFuncSetAttribute(k_mlp1, cudaFuncAttributeMaxDynamicSharedMemorySize, K1_SMEM);
    cudaFuncSetAttribute(k_mlp2, cudaFuncAttributeMaxDynamicSharedMemorySize, K2_SMEM);

    int n4 = (NN * 128) / 4;
    k_zero<<<(n4 + 255) / 256, 256>>>(n4);

    k_prep_w<<<512, 256>>>(op_w1, op_g, op_v, op_w2, nm_w1, nm_g, nm_v, nm_w2);
    k_prep_b1 <<<256, 32>>>(op_w1, op_b1, op_g, op_b, op_m, op_v);
    k_prep_nb1<<<128, 32>>>(nm_w1, nm_b1, nm_g, nm_b, nm_m, nm_v);

    k_mlp1<<<(T + 127) / 128, 512, K1_SMEM>>>(x, tok, op_b2, T);
    k_mlp2<<<(NN + 127) / 128, 512, K2_SMEM>>>(nm_b2, out, NN);
}

// round 10
// speedup vs baseline: 7.5941x; 1.1163x over previous
#include <cuda_runtime.h>
#include <cuda_fp16.h>
#include <cstdint>

typedef unsigned int u32;
typedef unsigned long long u64;

#define NMAX 100000

// ---------------- persistent scratch ----------------
__device__ float g_nf[NMAX * 128];
__device__ __align__(16) __half g_w1h[256 * 128];    // BN-folded, fp16 RN
__device__ __align__(16) __half g_w2h[256 * 256];
__device__ __align__(16) __half g_nw1h[128 * 128];   // BN-folded
__device__ __align__(16) __half g_nw2h[128 * 128];
__device__ float g_b1f[256];
__device__ float g_nb1f[128];

// ---------------- helpers ----------------
__device__ __forceinline__ u32 s2u(const void* p) {
    u32 a;
    asm("{ .reg .u64 t; cvta.to.shared.u64 t, %1; cvt.u32.u64 %0, t; }" : "=r"(a) : "l"(p));
    return a;
}
__device__ __forceinline__ void ldsm4(u32 a, u32& r0, u32& r1, u32& r2, u32& r3) {
    asm volatile("ldmatrix.sync.aligned.m8n8.x4.shared.b16 {%0,%1,%2,%3}, [%4];"
                 : "=r"(r0), "=r"(r1), "=r"(r2), "=r"(r3) : "r"(a));
}
__device__ __forceinline__ void sts32(u32 a, u32 v) {
    asm volatile("st.shared.b32 [%0], %1;" :: "r"(a), "r"(v));
}
__device__ __forceinline__ void sts64(u32 a, u32 x, u32 y) {
    asm volatile("st.shared.v2.b32 [%0], {%1,%2};" :: "r"(a), "r"(x), "r"(y));
}
__device__ __forceinline__ void cpa16(u32 dst, const void* src) {
    asm volatile("cp.async.cg.shared.global [%0], [%1], 16;" :: "r"(dst), "l"(src));
}
#define CP_COMMIT() asm volatile("cp.async.commit_group;")
#define CP_WAIT0()  asm volatile("cp.async.wait_group 0;")

__device__ __forceinline__ void mma16816(float* d, const u32* a, u32 b0, u32 b1) {
    asm volatile(
        "mma.sync.aligned.m16n8k16.row.col.f32.f16.f16.f32 "
        "{%0,%1,%2,%3}, {%4,%5,%6,%7}, {%8,%9}, {%0,%1,%2,%3};"
        : "+f"(d[0]), "+f"(d[1]), "+f"(d[2]), "+f"(d[3])
        : "r"(a[0]), "r"(a[1]), "r"(a[2]), "r"(a[3]), "r"(b0), "r"(b1));
}
__device__ __forceinline__ void red2(float* p, float a, float b) {
    asm volatile("red.global.add.v2.f32 [%0], {%1,%2};" :: "l"(p), "f"(a), "f"(b) : "memory");
}
__device__ __forceinline__ u32 pack2h(__half a, __half b) {
    return (u32)__half_as_ushort(a) | ((u32)__half_as_ushort(b) << 16);
}
__device__ __forceinline__ void splitpackh(float f0, float f1, u32& hi, u32& lo) {
    __half h0 = __float2half_rn(f0);
    __half h1 = __float2half_rn(f1);
    __half l0 = __float2half_rn(f0 - __half2float(h0));
    __half l1 = __float2half_rn(f1 - __half2float(h1));
    hi = pack2h(h0, h1); lo = pack2h(l0, l1);
}

// ---------------- prep ----------------
__global__ void k_zero(int n4) {
    int i = blockIdx.x * blockDim.x + threadIdx.x;
    if (i < n4) reinterpret_cast<float4*>(g_nf)[i] = make_float4(0.f, 0.f, 0.f, 0.f);
}
// blocks [0,512): weight convert; blocks [512,560): bias folding (8 warps/block, 1 n/warp)
__global__ void k_prep(const float* __restrict__ W1, const float* __restrict__ og,
                       const float* __restrict__ ov, const float* __restrict__ W2,
                       const float* __restrict__ NW1, const float* __restrict__ ng,
                       const float* __restrict__ nv, const float* __restrict__ NW2,
                       const float* __restrict__ ob1, const float* __restrict__ ob,
                       const float* __restrict__ om, const float* __restrict__ nb1,
                       const float* __restrict__ nb, const float* __restrict__ nm) {
    int blk = blockIdx.x;
    if (blk < 512) {
        int i = blk * 256 + threadIdx.x;
        if (i < 32768) {
            int k = i & 127;
            g_w1h[i] = __float2half_rn(W1[i] * (og[k] * rsqrtf(ov[k] + 1e-5f)));
        } else if (i < 98304) {
            int j = i - 32768;
            g_w2h[j] = __float2half_rn(W2[j]);
        } else if (i < 114688) {
            int j = i - 98304;
            int k = j & 127;
            g_nw1h[j] = __float2half_rn(NW1[j] * (ng[k] * rsqrtf(nv[k] + 1e-5f)));
        } else {
            int j = i - 114688;
            g_nw2h[j] = __float2half_rn(NW2[j]);
        }
    } else {
        int job = (blk - 512) * 8 + (threadIdx.x >> 5);
        int lane = threadIdx.x & 31;
        if (job < 256) {
            float s = 0.f;
            for (int k = lane; k < 128; k += 32) {
                float sc = og[k] * rsqrtf(ov[k] + 1e-5f);
                s += W1[job * 128 + k] * (ob[k] - om[k] * sc);
            }
            for (int o = 16; o; o >>= 1) s += __shfl_xor_sync(~0u, s, o);
            if (lane == 0) g_b1f[job] = ob1[job] + s;
        } else if (job < 384) {
            int n = job - 256;
            float s = 0.f;
            for (int k = lane; k < 128; k += 32) {
                float sc = ng[k] * rsqrtf(nv[k] + 1e-5f);
                s += NW1[n * 128 + k] * (nb[k] - nm[k] * sc);
            }
            for (int o = 16; o; o >>= 1) s += __shfl_xor_sync(~0u, s, o);
            if (lane == 0) g_nb1f[n] = nb1[n] + s;
        }
    }
}

// ---------------------------------------------------------------------------
// Kernel 1: MLP1 + scatter. 64 tokens/CTA, 256 threads (8 warps, 2x4),
// warp tile 32x64, fp16 2-term. 2 CTAs/SM for cross-CTA phase overlap.
// phase1: XAH 0(16K) XAL 16K(16K) W1H 32K(64K)
// phase2: A2H 0(32K) A2L 32K(32K) BUF0 64K(16K) BUF1 80K(16K)
// ---------------------------------------------------------------------------
#define K1_XAH   0u
#define K1_XAL   16384u
#define K1_W1H   32768u
#define K1_A2H   0u
#define K1_A2L   32768u
#define K1_BUF0  65536u
#define K1_BUF1  81920u
#define K1_B1    98304u
#define K1_B2    99328u
#define K1_SMEM  100352u

__global__ void __launch_bounds__(256, 2) k_mlp1(
    const float* __restrict__ x, const int* __restrict__ tok,
    const float* __restrict__ b2g, int T)
{
    extern __shared__ char sm[];
    const u32 sb = s2u(sm);
    const int tid = threadIdx.x, wid = tid >> 5, l = tid & 31;
    const int lr8 = l & 7;
    const int g = l >> 2, q = l & 3;
    const int wm = (wid & 1) * 32, wn = (wid >> 1) * 64;
    const int t0 = blockIdx.x * 64;
    const u32 keyX = (u32)lr8 << 4;
    const u32 aCX = (u32)((l >> 4) & 1) * 16;
    const u32 bCX = (u32)((l >> 3) & 1) * 16;

    ((float*)(sm + K1_B1))[tid] = g_b1f[tid];
    ((float*)(sm + K1_B2))[tid] = b2g[tid];

    // W1 resident (fp16, 256 rows x 256B = 64K)
    #pragma unroll
    for (int i = 0; i < 16; ++i) {
        int idx = tid + i * 256;                     // 0..4095
        int n = idx >> 4, seg = idx & 15;
        u32 o = (u32)n * 256 + (u32)seg * 16;
        cpa16(sb + K1_W1H + (o ^ (((u32)(n & 7)) << 4)), (const char*)g_w1h + o);
    }
    CP_COMMIT();

    // x tile [64,128] -> split fp16 hi/lo
    #pragma unroll
    for (int i = 0; i < 8; ++i) {
        int idx = tid + i * 256;                     // float4 0..2047
        int r = idx >> 5, c = (idx & 31) * 4;
        float4 v = make_float4(0.f, 0.f, 0.f, 0.f);
        if (t0 + r < T) v = *reinterpret_cast<const float4*>(x + (size_t)(t0 + r) * 128 + c);
        u32 h01, l01, h23, l23;
        splitpackh(v.x, v.y, h01, l01);
        splitpackh(v.z, v.w, h23, l23);
        u32 o = (u32)r * 256 + (((u32)c * 2) ^ (((u32)(r & 7)) << 4));
        sts64(sb + K1_XAH + o, h01, h23);
        sts64(sb + K1_XAL + o, l01, l23);
    }
    CP_WAIT0();
    __syncthreads();

    // ---------------- GEMM1: y1 = x @ W1^T ----------------
    float acc[2][8][4];
    #pragma unroll
    for (int mt = 0; mt < 2; ++mt)
        #pragma unroll
        for (int nt = 0; nt < 8; ++nt)
            #pragma unroll
            for (int j = 0; j < 4; ++j) acc[mt][nt][j] = 0.f;

    {
        const u32 PA = K1_XAH + (u32)(wm + lr8 + ((l >> 3) & 1) * 8) * 256u + keyX;
        const u32 PB = K1_W1H + (u32)(wn + lr8 + ((l >> 4) & 1) * 8) * 256u + keyX;
        #pragma unroll
        for (int kt = 0; kt < 8; ++kt) {
            u32 ca = (u32)kt * 32 + aCX, cb = (u32)kt * 32 + bCX;
            u32 Ah[2][4], Al[2][4];
            ldsm4(sb + ((PA)          ^ ca), Ah[0][0], Ah[0][1], Ah[0][2], Ah[0][3]);
            ldsm4(sb + ((PA + 4096u)  ^ ca), Ah[1][0], Ah[1][1], Ah[1][2], Ah[1][3]);
            ldsm4(sb + ((PA + 16384u) ^ ca), Al[0][0], Al[0][1], Al[0][2], Al[0][3]);
            ldsm4(sb + ((PA + 20480u) ^ ca), Al[1][0], Al[1][1], Al[1][2], Al[1][3]);
            #pragma unroll
            for (int ntg = 0; ntg < 4; ++ntg) {
                u32 bh[4];
                ldsm4(sb + ((PB + (u32)ntg * 4096u) ^ cb), bh[0], bh[1], bh[2], bh[3]);
                #pragma unroll
                for (int sub = 0; sub < 2; ++sub) {
                    int nt = ntg * 2 + sub;
                    #pragma unroll
                    for (int mt = 0; mt < 2; ++mt) {
                        mma16816(acc[mt][nt], Ah[mt], bh[sub * 2], bh[sub * 2 + 1]);
                        mma16816(acc[mt][nt], Al[mt], bh[sub * 2], bh[sub * 2 + 1]);
                    }
                }
            }
        }
    }
    __syncthreads();   // GEMM1 reads done; regions reusable

    // prefetch W2 slab 0 (k 0..31): 256 rows x 64B
    #pragma unroll
    for (int i = 0; i < 4; ++i) {
        int idx = tid + i * 256;                     // 0..1023
        int n = idx >> 2, seg = idx & 3;
        u32 o = (u32)n * 64 + (u32)seg * 16;
        cpa16(sb + K1_BUF0 + (o ^ (((u32)(n & 7)) << 4)),
              (const char*)g_w2h + (size_t)n * 512 + (size_t)seg * 16);
    }
    CP_COMMIT();

    // epilogue1: A2 = split_fp16(relu(y1 + b1f)), 64 rows x 512B
    {
        const float* b1s = (const float*)(sm + K1_B1);
        const u32 kr = (u32)g << 4;
        #pragma unroll
        for (int mt = 0; mt < 2; ++mt) {
            u32 row = (u32)(wm + mt * 16 + g);
            #pragma unroll
            for (int nt = 0; nt < 8; ++nt) {
                int c0 = wn + nt * 8 + q * 2;
                float bx = b1s[c0], by = b1s[c0 + 1];
                float f0 = fmaxf(acc[mt][nt][0] + bx, 0.f);
                float f1 = fmaxf(acc[mt][nt][1] + by, 0.f);
                float f2 = fmaxf(acc[mt][nt][2] + bx, 0.f);
                float f3 = fmaxf(acc[mt][nt][3] + by, 0.f);
                u32 col = ((u32)c0 * 2) ^ kr;
                u32 oA = row * 512 + col;
                u32 oB = (row + 8) * 512 + col;
                u32 hi, lo;
                splitpackh(f0, f1, hi, lo);
                sts32(sb + K1_A2H + oA, hi); sts32(sb + K1_A2L + oA, lo);
                splitpackh(f2, f3, hi, lo);
                sts32(sb + K1_A2H + oB, hi); sts32(sb + K1_A2L + oB, lo);
            }
        }
    }
    CP_WAIT0();
    __syncthreads();

    // ---------------- GEMM2: y2 = relu(y1) @ W2^T (K=256, 8 slabs of 32) ----
    #pragma unroll
    for (int mt = 0; mt < 2; ++mt)
        #pragma unroll
        for (int nt = 0; nt < 8; ++nt)
            #pragma unroll
            for (int j = 0; j < 4; ++j) acc[mt][nt][j] = 0.f;

    {
        const u32 PA2 = K1_A2H + (u32)(wm + lr8 + ((l >> 3) & 1) * 8) * 512u + keyX;
        const u32 PW2 = ((u32)(wn + lr8 + ((l >> 4) & 1) * 8) * 64u) ^ keyX;
        #pragma unroll 1
        for (int s = 0; s < 8; ++s) {
            if (s < 7) {
                u32 dB = (s & 1) ? K1_BUF0 : K1_BUF1;
                #pragma unroll
                for (int i = 0; i < 4; ++i) {
                    int idx = tid + i * 256;
                    int n = idx >> 2, seg = idx & 3;
                    u32 o = (u32)n * 64 + (u32)seg * 16;
                    size_t src = (size_t)n * 512 + (size_t)(s + 1) * 64 + (size_t)seg * 16;
                    cpa16(sb + dB + (o ^ (((u32)(n & 7)) << 4)), (const char*)g_w2h + src);
                }
                CP_COMMIT();
            }
            u32 bB = sb + ((s & 1) ? K1_BUF1 : K1_BUF0);
            #pragma unroll
            for (int ktL = 0; ktL < 2; ++ktL) {
                int kt = s * 2 + ktL;
                u32 ca = (u32)kt * 32 + aCX;
                u32 cw = (u32)ktL * 32 + bCX;
                u32 Ah[2][4], Al[2][4];
                ldsm4(sb + ((PA2)          ^ ca), Ah[0][0], Ah[0][1], Ah[0][2], Ah[0][3]);
                ldsm4(sb + ((PA2 + 8192u)  ^ ca), Ah[1][0], Ah[1][1], Ah[1][2], Ah[1][3]);
                ldsm4(sb + ((PA2 + 32768u) ^ ca), Al[0][0], Al[0][1], Al[0][2], Al[0][3]);
                ldsm4(sb + ((PA2 + 40960u) ^ ca), Al[1][0], Al[1][1], Al[1][2], Al[1][3]);
                #pragma unroll
                for (int ntg = 0; ntg < 4; ++ntg) {
                    u32 bh[4];
                    ldsm4(bB + ((PW2 + (u32)ntg * 1024u) ^ cw), bh[0], bh[1], bh[2], bh[3]);
                    #pragma unroll
                    for (int sub = 0; sub < 2; ++sub) {
                        int nt = ntg * 2 + sub;
                        #pragma unroll
                        for (int mt = 0; mt < 2; ++mt) {
                            mma16816(acc[mt][nt], Ah[mt], bh[sub * 2], bh[sub * 2 + 1]);
                            mma16816(acc[mt][nt], Al[mt], bh[sub * 2], bh[sub * 2 + 1]);
                        }
                    }
                }
            }
            if (s < 7) CP_WAIT0();
            __syncthreads();
        }
    }

    // ---------------- scatter ----------------
    {
        const float* b2s = (const float*)(sm + K1_B2);
        int cofs = (wn < 128) ? 0 : 128;
        #pragma unroll
        for (int mt = 0; mt < 2; ++mt) {
            int tA = t0 + wm + mt * 16 + g;
            int tB = tA + 8;
            float* rowA = nullptr; float* rowB = nullptr;
            if (tA < T) {
                int nd = (cofs == 0) ? tok[tA] : tok[T + tA];
                rowA = g_nf + (size_t)nd * 128;
            }
            if (tB < T) {
                int nd = (cofs == 0) ? tok[tB] : tok[T + tB];
                rowB = g_nf + (size_t)nd * 128;
            }
            #pragma unroll
            for (int nt = 0; nt < 8; ++nt) {
                int c0 = wn + nt * 8 + q * 2;
                float bx = b2s[c0], by = b2s[c0 + 1];
                int cl = c0 - cofs;
                if (rowA) red2(rowA + cl, acc[mt][nt][0] + bx, acc[mt][nt][1] + by);
                if (rowB) red2(rowB + cl, acc[mt][nt][2] + bx, acc[mt][nt][3] + by);
            }
        }
    }
}

// ---------------------------------------------------------------------------
// Kernel 2: MLP2. 64 nodes/CTA, 256 threads (8 warps, 2x4), warp tile 32x32.
// 2 CTAs/SM. XAH 0(16K) XAL 16K(16K) WH 32K(32K)
// ---------------------------------------------------------------------------
#define K2_XAH  0u
#define K2_XAL  16384u
#define K2_WH   32768u
#define K2_B1   65536u
#define K2_B2   66048u
#define K2_SMEM 66560u

__global__ void __launch_bounds__(256, 2) k_mlp2(
    const float* __restrict__ b2g, float* __restrict__ out, int NN)
{
    extern __shared__ char sm[];
    const u32 sb = s2u(sm);
    const int tid = threadIdx.x, wid = tid >> 5, l = tid & 31;
    const int lr8 = l & 7;
    const int g = l >> 2, q = l & 3;
    const int wm = (wid & 1) * 32, wn = (wid >> 1) * 32;
    const int n0 = blockIdx.x * 64;
    const u32 keyX = (u32)lr8 << 4;
    const u32 aCX = (u32)((l >> 4) & 1) * 16;
    const u32 bCX = (u32)((l >> 3) & 1) * 16;

    if (tid < 128) {
        ((float*)(sm + K2_B1))[tid] = g_nb1f[tid];
        ((float*)(sm + K2_B2))[tid] = b2g[tid];
    }

    // W1' resident (128 rows x 256B = 32K)
    #pragma unroll
    for (int i = 0; i < 8; ++i) {
        int idx = tid + i * 256;                      // 0..2047
        int n = idx >> 4, seg = idx & 15;
        u32 o = (u32)n * 256 + (u32)seg * 16;
        cpa16(sb + K2_WH + (o ^ (((u32)(n & 7)) << 4)), (const char*)g_nw1h + o);
    }
    CP_COMMIT();

    // nf tile [64,128] -> split fp16
    #pragma unroll
    for (int i = 0; i < 8; ++i) {
        int idx = tid + i * 256;
        int r = idx >> 5, c = (idx & 31) * 4;
        float4 v = make_float4(0.f, 0.f, 0.f, 0.f);
        if (n0 + r < NN) v = *reinterpret_cast<const float4*>(g_nf + (size_t)(n0 + r) * 128 + c);
        u32 h01, l01, h23, l23;
        splitpackh(v.x, v.y, h01, l01);
        splitpackh(v.z, v.w, h23, l23);
        u32 o = (u32)r * 256 + (((u32)c * 2) ^ (((u32)(r & 7)) << 4));
        sts64(sb + K2_XAH + o, h01, h23);
        sts64(sb + K2_XAL + o, l01, l23);
    }
    CP_WAIT0();
    __syncthreads();

    float acc[2][4][4];
    const u32 PA = K2_XAH + (u32)(wm + lr8 + ((l >> 3) & 1) * 8) * 256u + keyX;
    const u32 PB = K2_WH  + (u32)(wn + lr8 + ((l >> 4) & 1) * 8) * 256u + keyX;

    // ---- GEMM1 ----
    #pragma unroll
    for (int mt = 0; mt < 2; ++mt)
        #pragma unroll
        for (int nt = 0; nt < 4; ++nt)
            #pragma unroll
            for (int j = 0; j < 4; ++j) acc[mt][nt][j] = 0.f;

    #pragma unroll
    for (int kt = 0; kt < 8; ++kt) {
        u32 ca = (u32)kt * 32 + aCX, cb = (u32)kt * 32 + bCX;
        u32 Ah[2][4], Al[2][4];
        ldsm4(sb + ((PA)          ^ ca), Ah[0][0], Ah[0][1], Ah[0][2], Ah[0][3]);
        ldsm4(sb + ((PA + 4096u)  ^ ca), Ah[1][0], Ah[1][1], Ah[1][2], Ah[1][3]);
        ldsm4(sb + ((PA + 16384u) ^ ca), Al[0][0], Al[0][1], Al[0][2], Al[0][3]);
        ldsm4(sb + ((PA + 20480u) ^ ca), Al[1][0], Al[1][1], Al[1][2], Al[1][3]);
        #pragma unroll
        for (int ntg = 0; ntg < 2; ++ntg) {
            u32 bh[4];
            ldsm4(sb + ((PB + (u32)ntg * 4096u) ^ cb), bh[0], bh[1], bh[2], bh[3]);
            #pragma unroll
            for (int sub = 0; sub < 2; ++sub) {
                int nt = ntg * 2 + sub;
                #pragma unroll
                for (int mt = 0; mt < 2; ++mt) {
                    mma16816(acc[mt][nt], Ah[mt], bh[sub * 2], bh[sub * 2 + 1]);
                    mma16816(acc[mt][nt], Al[mt], bh[sub * 2], bh[sub * 2 + 1]);
                }
            }
        }
    }
    __syncthreads();

    // prefetch W2' over WH
    #pragma unroll
    for (int i = 0; i < 8; ++i) {
        int idx = tid + i * 256;
        int n = idx >> 4, seg = idx & 15;
        u32 o = (u32)n * 256 + (u32)seg * 16;
        cpa16(sb + K2_WH + (o ^ (((u32)(n & 7)) << 4)), (const char*)g_nw2h + o);
    }
    CP_COMMIT();

    // epilogue1 -> A2 over XA (stride 256B)
    {
        const float* b1s = (const float*)(sm + K2_B1);
        const u32 kr = (u32)g << 4;
        #pragma unroll
        for (int mt = 0; mt < 2; ++mt) {
            u32 row = (u32)(wm + mt * 16 + g);
            #pragma unroll
            for (int nt = 0; nt < 4; ++nt) {
                int c0 = wn + nt * 8 + q * 2;
                float bx = b1s[c0], by = b1s[c0 + 1];
                float f0 = fmaxf(acc[mt][nt][0] + bx, 0.f);
                float f1 = fmaxf(acc[mt][nt][1] + by, 0.f);
                float f2 = fmaxf(acc[mt][nt][2] + bx, 0.f);
                float f3 = fmaxf(acc[mt][nt][3] + by, 0.f);
                u32 col = ((u32)c0 * 2) ^ kr;
                u32 oA = row * 256 + col;
                u32 oB = (row + 8) * 256 + col;
                u32 hi, lo;
                splitpackh(f0, f1, hi, lo);
                sts32(sb + K2_XAH + oA, hi); sts32(sb + K2_XAL + oA, lo);
                splitpackh(f2, f3, hi, lo);
                sts32(sb + K2_XAH + oB, hi); sts32(sb + K2_XAL + oB, lo);
            }
        }
    }
    CP_WAIT0();
    __syncthreads();

    // ---- GEMM2 ----
    #pragma unroll
    for (int mt = 0; mt < 2; ++mt)
        #pragma unroll
        for (int nt = 0; nt < 4; ++nt)
            #pragma unroll
            for (int j = 0; j < 4; ++j) acc[mt][nt][j] = 0.f;

    #pragma unroll
    for (int kt = 0; kt < 8; ++kt) {
        u32 ca = (u32)kt * 32 + aCX, cb = (u32)kt * 32 + bCX;
        u32 Ah[2][4], Al[2][4];
        ldsm4(sb + ((PA)          ^ ca), Ah[0][0], Ah[0][1], Ah[0][2], Ah[0][3]);
        ldsm4(sb + ((PA + 4096u)  ^ ca), Ah[1][0], Ah[1][1], Ah[1][2], Ah[1][3]);
        ldsm4(sb + ((PA + 16384u) ^ ca), Al[0][0], Al[0][1], Al[0][2], Al[0][3]);
        ldsm4(sb + ((PA + 20480u) ^ ca), Al[1][0], Al[1][1], Al[1][2], Al[1][3]);
        #pragma unroll
        for (int ntg = 0; ntg < 2; ++ntg) {
            u32 bh[4];
            ldsm4(sb + ((PB + (u32)ntg * 4096u) ^ cb), bh[0], bh[1], bh[2], bh[3]);
            #pragma unroll
            for (int sub = 0; sub < 2; ++sub) {
                int nt = ntg * 2 + sub;
                #pragma unroll
                for (int mt = 0; mt < 2; ++mt) {
                    mma16816(acc[mt][nt], Ah[mt], bh[sub * 2], bh[sub * 2 + 1]);
                    mma16816(acc[mt][nt], Al[mt], bh[sub * 2], bh[sub * 2 + 1]);
                }
            }
        }
    }

    // output
    {
        const float* b2s = (const float*)(sm + K2_B2);
        #pragma unroll
        for (int mt = 0; mt < 2; ++mt) {
            int rA = n0 + wm + mt * 16 + g;
            int rB = rA + 8;
            #pragma unroll
            for (int nt = 0; nt < 4; ++nt) {
                int c0 = wn + nt * 8 + q * 2;
                float bx = b2s[c0], by = b2s[c0 + 1];
                if (rA < NN)
                    *reinterpret_cast<float2*>(out + (size_t)rA * 128 + c0) =
                        make_float2(acc[mt][nt][0] + bx, acc[mt][nt][1] + by);
                if (rB < NN)
                    *reinterpret_cast<float2*>(out + (size_t)rB * 128 + c0) =
                        make_float2(acc[mt][nt][2] + bx, acc[mt][nt][3] + by);
            }
        }
    }
}

// ---------------------------------------------------------------------------
extern "C" void kernel_launch(void* const* d_in, const int* in_sizes, int n_in,
                              void* d_out, int out_size) {
    const float* x    = (const float*)d_in[0];
    const int*   tok  = (const int*)d_in[3];   // int32 (JAX x64 disabled)
    const float* op_g  = (const float*)d_in[4];
    const float* op_b  = (const float*)d_in[5];
    const float* op_m  = (const float*)d_in[6];
    const float* op_v  = (const float*)d_in[7];
    const float* op_w1 = (const float*)d_in[8];
    const float* op_b1 = (const float*)d_in[9];
    const float* op_w2 = (const float*)d_in[10];
    const float* op_b2 = (const float*)d_in[11];
    const float* nm_g  = (const float*)d_in[12];
    const float* nm_b  = (const float*)d_in[13];
    const float* nm_m  = (const float*)d_in[14];
    const float* nm_v  = (const float*)d_in[15];
    const float* nm_w1 = (const float*)d_in[16];
    const float* nm_b1 = (const float*)d_in[17];
    const float* nm_w2 = (const float*)d_in[18];
    const float* nm_b2 = (const float*)d_in[19];

    int T  = in_sizes[0] / 128;
    int NN = in_sizes[2];
    float* out = (float*)d_out;

    cudaFuncSetAttribute(k_mlp1, cudaFuncAttributeMaxDynamicSharedMemorySize, K1_SMEM);
    cudaFuncSetAttribute(k_mlp2, cudaFuncAttributeMaxDynamicSharedMemorySize, K2_SMEM);

    int n4 = (NN * 128) / 4;
    k_zero<<<(n4 + 255) / 256, 256>>>(n4);

    k_prep<<<560, 256>>>(op_w1, op_g, op_v, op_w2, nm_w1, nm_g, nm_v, nm_w2,
                         op_b1, op_b, op_m, nm_b1, nm_b, nm_m);

    k_mlp1<<<(T + 63) / 64, 256, K1_SMEM>>>(x, tok, op_b2, T);
    k_mlp2<<<(NN + 63) / 64, 256, K2_SMEM>>>(nm_b2, out, NN);
}

// round 11
// speedup vs baseline: 10.2201x; 1.3458x over previous
#include <cuda_runtime.h>
#include <cuda_fp16.h>
#include <cstdint>

typedef unsigned int u32;
typedef unsigned long long u64;

#define NMAX 100000

// ---------------- persistent scratch ----------------
__device__ float g_nf[NMAX * 128];
__device__ __align__(16) __half g_w1h[256 * 128];    // BN-folded, fp16 RN
__device__ __align__(16) __half g_w2h[256 * 256];
__device__ __align__(16) __half g_nw1h[128 * 128];   // BN-folded
__device__ __align__(16) __half g_nw2h[128 * 128];
__device__ float g_b1f[256];
__device__ float g_nb1f[128];

// ---------------- helpers ----------------
__device__ __forceinline__ u32 s2u(const void* p) {
    u32 a;
    asm("{ .reg .u64 t; cvta.to.shared.u64 t, %1; cvt.u32.u64 %0, t; }" : "=r"(a) : "l"(p));
    return a;
}
__device__ __forceinline__ void ldsm4(u32 a, u32& r0, u32& r1, u32& r2, u32& r3) {
    asm volatile("ldmatrix.sync.aligned.m8n8.x4.shared.b16 {%0,%1,%2,%3}, [%4];"
                 : "=r"(r0), "=r"(r1), "=r"(r2), "=r"(r3) : "r"(a));
}
__device__ __forceinline__ void sts32(u32 a, u32 v) {
    asm volatile("st.shared.b32 [%0], %1;" :: "r"(a), "r"(v));
}
__device__ __forceinline__ void sts64(u32 a, u32 x, u32 y) {
    asm volatile("st.shared.v2.b32 [%0], {%1,%2};" :: "r"(a), "r"(x), "r"(y));
}
__device__ __forceinline__ void cpa16(u32 dst, const void* src) {
    asm volatile("cp.async.cg.shared.global [%0], [%1], 16;" :: "r"(dst), "l"(src));
}
#define CP_COMMIT() asm volatile("cp.async.commit_group;")
#define CP_WAIT0()  asm volatile("cp.async.wait_group 0;")

__device__ __forceinline__ void mma16816(float* d, const u32* a, u32 b0, u32 b1) {
    asm volatile(
        "mma.sync.aligned.m16n8k16.row.col.f32.f16.f16.f32 "
        "{%0,%1,%2,%3}, {%4,%5,%6,%7}, {%8,%9}, {%0,%1,%2,%3};"
        : "+f"(d[0]), "+f"(d[1]), "+f"(d[2]), "+f"(d[3])
        : "r"(a[0]), "r"(a[1]), "r"(a[2]), "r"(a[3]), "r"(b0), "r"(b1));
}
__device__ __forceinline__ void red2(float* p, float a, float b) {
    asm volatile("red.global.add.v2.f32 [%0], {%1,%2};" :: "l"(p), "f"(a), "f"(b) : "memory");
}
__device__ __forceinline__ void red4(float* p, float a, float b, float c, float d) {
    asm volatile("red.global.add.v4.f32 [%0], {%1,%2,%3,%4};"
                 :: "l"(p), "f"(a), "f"(b), "f"(c), "f"(d) : "memory");
}
__device__ __forceinline__ u32 pack2h(__half a, __half b) {
    return (u32)__half_as_ushort(a) | ((u32)__half_as_ushort(b) << 16);
}
__device__ __forceinline__ void splitpackh(float f0, float f1, u32& hi, u32& lo) {
    __half h0 = __float2half_rn(f0);
    __half h1 = __float2half_rn(f1);
    __half l0 = __float2half_rn(f0 - __half2float(h0));
    __half l1 = __float2half_rn(f1 - __half2float(h1));
    hi = pack2h(h0, h1); lo = pack2h(l0, l1);
}

// ---------------- prep ----------------
__global__ void k_zero(int n4) {
    int i = blockIdx.x * blockDim.x + threadIdx.x;
    if (i < n4) reinterpret_cast<float4*>(g_nf)[i] = make_float4(0.f, 0.f, 0.f, 0.f);
}
// blocks [0,512): weight convert; blocks [512,560): bias folding
__global__ void k_prep(const float* __restrict__ W1, const float* __restrict__ og,
                       const float* __restrict__ ov, const float* __restrict__ W2,
                       const float* __restrict__ NW1, const float* __restrict__ ng,
                       const float* __restrict__ nv, const float* __restrict__ NW2,
                       const float* __restrict__ ob1, const float* __restrict__ ob,
                       const float* __restrict__ om, const float* __restrict__ nb1,
                       const float* __restrict__ nb, const float* __restrict__ nm) {
    int blk = blockIdx.x;
    if (blk < 512) {
        int i = blk * 256 + threadIdx.x;
        if (i < 32768) {
            int k = i & 127;
            g_w1h[i] = __float2half_rn(W1[i] * (og[k] * rsqrtf(ov[k] + 1e-5f)));
        } else if (i < 98304) {
            int j = i - 32768;
            g_w2h[j] = __float2half_rn(W2[j]);
        } else if (i < 114688) {
            int j = i - 98304;
            int k = j & 127;
            g_nw1h[j] = __float2half_rn(NW1[j] * (ng[k] * rsqrtf(nv[k] + 1e-5f)));
        } else {
            int j = i - 114688;
            g_nw2h[j] = __float2half_rn(NW2[j]);
        }
    } else {
        int job = (blk - 512) * 8 + (threadIdx.x >> 5);
        int lane = threadIdx.x & 31;
        if (job < 256) {
            float s = 0.f;
            for (int k = lane; k < 128; k += 32) {
                float sc = og[k] * rsqrtf(ov[k] + 1e-5f);
                s += W1[job * 128 + k] * (ob[k] - om[k] * sc);
            }
            for (int o = 16; o; o >>= 1) s += __shfl_xor_sync(~0u, s, o);
            if (lane == 0) g_b1f[job] = ob1[job] + s;
        } else if (job < 384) {
            int n = job - 256;
            float s = 0.f;
            for (int k = lane; k < 128; k += 32) {
                float sc = ng[k] * rsqrtf(nv[k] + 1e-5f);
                s += NW1[n * 128 + k] * (nb[k] - nm[k] * sc);
            }
            for (int o = 16; o; o >>= 1) s += __shfl_xor_sync(~0u, s, o);
            if (lane == 0) g_nb1f[n] = nb1[n] + s;
        }
    }
}

// ---------------------------------------------------------------------------
// Kernel 1: MLP1 + scatter. 64 tokens/CTA, 256 threads (8 warps, 2x4),
// warp tile 32x64, 2 CTAs/SM.
// GEMM1: 2-term (x hi+lo). GEMM2: 1-term (A2 hi only) — fp16-round error of
// post-ReLU y1 is ~1.2e-4 RMS, quadrature-safe vs 1e-3 bar.
// phase1: XAH 0(16K) XAL 16K(16K) W1H 32K(64K)
// phase2: A2H 0(32K) BUF0 32K(32K,k=64 slab) BUF1 64K(32K)
// ---------------------------------------------------------------------------
#define K1_XAH   0u
#define K1_XAL   16384u
#define K1_W1H   32768u
#define K1_A2H   0u
#define K1_BUF0  32768u
#define K1_BUF1  65536u
#define K1_B1    98304u
#define K1_B2    99328u
#define K1_SMEM  100352u

__global__ void __launch_bounds__(256, 2) k_mlp1(
    const float* __restrict__ x, const int* __restrict__ tok,
    const float* __restrict__ b2g, int T)
{
    extern __shared__ char sm[];
    const u32 sb = s2u(sm);
    const int tid = threadIdx.x, wid = tid >> 5, l = tid & 31;
    const int lr8 = l & 7;
    const int g = l >> 2, q = l & 3;
    const int wm = (wid & 1) * 32, wn = (wid >> 1) * 64;
    const int t0 = blockIdx.x * 64;
    const u32 keyX = (u32)lr8 << 4;
    const u32 aCX = (u32)((l >> 4) & 1) * 16;
    const u32 bCX = (u32)((l >> 3) & 1) * 16;

    ((float*)(sm + K1_B1))[tid] = g_b1f[tid];
    ((float*)(sm + K1_B2))[tid] = b2g[tid];

    // W1 resident (fp16, 256 rows x 256B = 64K)
    #pragma unroll
    for (int i = 0; i < 16; ++i) {
        int idx = tid + i * 256;                     // 0..4095
        int n = idx >> 4, seg = idx & 15;
        u32 o = (u32)n * 256 + (u32)seg * 16;
        cpa16(sb + K1_W1H + (o ^ (((u32)(n & 7)) << 4)), (const char*)g_w1h + o);
    }
    CP_COMMIT();

    // x tile [64,128] -> split fp16 hi/lo
    #pragma unroll
    for (int i = 0; i < 8; ++i) {
        int idx = tid + i * 256;                     // float4 0..2047
        int r = idx >> 5, c = (idx & 31) * 4;
        float4 v = make_float4(0.f, 0.f, 0.f, 0.f);
        if (t0 + r < T) v = *reinterpret_cast<const float4*>(x + (size_t)(t0 + r) * 128 + c);
        u32 h01, l01, h23, l23;
        splitpackh(v.x, v.y, h01, l01);
        splitpackh(v.z, v.w, h23, l23);
        u32 o = (u32)r * 256 + (((u32)c * 2) ^ (((u32)(r & 7)) << 4));
        sts64(sb + K1_XAH + o, h01, h23);
        sts64(sb + K1_XAL + o, l01, l23);
    }
    CP_WAIT0();
    __syncthreads();

    // ---------------- GEMM1: y1 = x @ W1^T (2-term) ----------------
    float acc[2][8][4];
    #pragma unroll
    for (int mt = 0; mt < 2; ++mt)
        #pragma unroll
        for (int nt = 0; nt < 8; ++nt)
            #pragma unroll
            for (int j = 0; j < 4; ++j) acc[mt][nt][j] = 0.f;

    {
        const u32 PA = K1_XAH + (u32)(wm + lr8 + ((l >> 3) & 1) * 8) * 256u + keyX;
        const u32 PB = K1_W1H + (u32)(wn + lr8 + ((l >> 4) & 1) * 8) * 256u + keyX;
        #pragma unroll
        for (int kt = 0; kt < 8; ++kt) {
            u32 ca = (u32)kt * 32 + aCX, cb = (u32)kt * 32 + bCX;
            u32 Ah[2][4], Al[2][4];
            ldsm4(sb + ((PA)          ^ ca), Ah[0][0], Ah[0][1], Ah[0][2], Ah[0][3]);
            ldsm4(sb + ((PA + 4096u)  ^ ca), Ah[1][0], Ah[1][1], Ah[1][2], Ah[1][3]);
            ldsm4(sb + ((PA + 16384u) ^ ca), Al[0][0], Al[0][1], Al[0][2], Al[0][3]);
            ldsm4(sb + ((PA + 20480u) ^ ca), Al[1][0], Al[1][1], Al[1][2], Al[1][3]);
            #pragma unroll
            for (int ntg = 0; ntg < 4; ++ntg) {
                u32 bh[4];
                ldsm4(sb + ((PB + (u32)ntg * 4096u) ^ cb), bh[0], bh[1], bh[2], bh[3]);
                #pragma unroll
                for (int sub = 0; sub < 2; ++sub) {
                    int nt = ntg * 2 + sub;
                    #pragma unroll
                    for (int mt = 0; mt < 2; ++mt) {
                        mma16816(acc[mt][nt], Ah[mt], bh[sub * 2], bh[sub * 2 + 1]);
                        mma16816(acc[mt][nt], Al[mt], bh[sub * 2], bh[sub * 2 + 1]);
                    }
                }
            }
        }
    }
    __syncthreads();   // GEMM1 reads done; XA + W1H regions reusable

    // prefetch W2 slab 0 (k 0..63): 256 rows x 128B = 32K -> BUF0
    #pragma unroll
    for (int i = 0; i < 8; ++i) {
        int idx = tid + i * 256;                     // 0..2047
        int n = idx >> 3, seg = idx & 7;
        u32 o = (u32)n * 128 + (u32)seg * 16;
        cpa16(sb + K1_BUF0 + (o ^ (((u32)(n & 7)) << 4)),
              (const char*)g_w2h + (size_t)n * 512 + (size_t)seg * 16);
    }
    CP_COMMIT();

    // epilogue1: A2 = fp16(relu(y1 + b1f)) hi only, 64 rows x 512B
    {
        const float* b1s = (const float*)(sm + K1_B1);
        const u32 kr = (u32)g << 4;
        #pragma unroll
        for (int mt = 0; mt < 2; ++mt) {
            u32 row = (u32)(wm + mt * 16 + g);
            #pragma unroll
            for (int nt = 0; nt < 8; ++nt) {
                int c0 = wn + nt * 8 + q * 2;
                float bx = b1s[c0], by = b1s[c0 + 1];
                float f0 = fmaxf(acc[mt][nt][0] + bx, 0.f);
                float f1 = fmaxf(acc[mt][nt][1] + by, 0.f);
                float f2 = fmaxf(acc[mt][nt][2] + bx, 0.f);
                float f3 = fmaxf(acc[mt][nt][3] + by, 0.f);
                u32 col = ((u32)c0 * 2) ^ kr;
                sts32(sb + K1_A2H + row * 512 + col,
                      pack2h(__float2half_rn(f0), __float2half_rn(f1)));
                sts32(sb + K1_A2H + (row + 8) * 512 + col,
                      pack2h(__float2half_rn(f2), __float2half_rn(f3)));
            }
        }
    }
    CP_WAIT0();
    __syncthreads();

    // ---------------- GEMM2: y2 = A2hi @ W2^T (K=256, 4 slabs of 64) ----
    #pragma unroll
    for (int mt = 0; mt < 2; ++mt)
        #pragma unroll
        for (int nt = 0; nt < 8; ++nt)
            #pragma unroll
            for (int j = 0; j < 4; ++j) acc[mt][nt][j] = 0.f;

    {
        const u32 PA2 = K1_A2H + (u32)(wm + lr8 + ((l >> 3) & 1) * 8) * 512u + keyX;
        const u32 PW2 = ((u32)(wn + lr8 + ((l >> 4) & 1) * 8) * 128u) ^ keyX;
        #pragma unroll 1
        for (int s = 0; s < 4; ++s) {
            if (s < 3) {
                u32 dB = (s & 1) ? K1_BUF0 : K1_BUF1;
                #pragma unroll
                for (int i = 0; i < 8; ++i) {
                    int idx = tid + i * 256;
                    int n = idx >> 3, seg = idx & 7;
                    u32 o = (u32)n * 128 + (u32)seg * 16;
                    size_t src = (size_t)n * 512 + (size_t)(s + 1) * 128 + (size_t)seg * 16;
                    cpa16(sb + dB + (o ^ (((u32)(n & 7)) << 4)), (const char*)g_w2h + src);
                }
                CP_COMMIT();
            }
            u32 bB = sb + ((s & 1) ? K1_BUF1 : K1_BUF0);
            #pragma unroll
            for (int ktL = 0; ktL < 4; ++ktL) {
                int kt = s * 4 + ktL;
                u32 ca = (u32)kt * 32 + aCX;
                u32 cw = (u32)ktL * 32 + bCX;
                u32 Ah[2][4];
                ldsm4(sb + ((PA2)         ^ ca), Ah[0][0], Ah[0][1], Ah[0][2], Ah[0][3]);
                ldsm4(sb + ((PA2 + 8192u) ^ ca), Ah[1][0], Ah[1][1], Ah[1][2], Ah[1][3]);
                #pragma unroll
                for (int ntg = 0; ntg < 4; ++ntg) {
                    u32 bh[4];
                    ldsm4(bB + ((PW2 + (u32)ntg * 2048u) ^ cw), bh[0], bh[1], bh[2], bh[3]);
                    #pragma unroll
                    for (int sub = 0; sub < 2; ++sub) {
                        int nt = ntg * 2 + sub;
                        #pragma unroll
                        for (int mt = 0; mt < 2; ++mt)
                            mma16816(acc[mt][nt], Ah[mt], bh[sub * 2], bh[sub * 2 + 1]);
                    }
                }
            }
            if (s < 3) CP_WAIT0();
            __syncthreads();
        }
    }

    // ---------------- scatter: v4 via lane-pair merge ----------------
    {
        const float* b2s = (const float*)(sm + K1_B2);
        int cofs = (wn < 128) ? 0 : 128;
        const bool evenq = ((q & 1) == 0);
        #pragma unroll
        for (int mt = 0; mt < 2; ++mt) {
            int tA = t0 + wm + mt * 16 + g;
            int tB = tA + 8;
            float* rowA = nullptr; float* rowB = nullptr;
            if (tA < T) {
                int nd = (cofs == 0) ? tok[tA] : tok[T + tA];
                rowA = g_nf + (size_t)nd * 128;
            }
            if (tB < T) {
                int nd = (cofs == 0) ? tok[tB] : tok[T + tB];
                rowB = g_nf + (size_t)nd * 128;
            }
            #pragma unroll
            for (int nt = 0; nt < 8; ++nt) {
                int c0 = wn + nt * 8 + q * 2;
                float bx = b2s[c0], by = b2s[c0 + 1];
                float a0 = acc[mt][nt][0] + bx;
                float a1 = acc[mt][nt][1] + by;
                float a2 = acc[mt][nt][2] + bx;
                float a3 = acc[mt][nt][3] + by;
                // partner lane (l^1) holds cols c0+2, c0+3 of the same rows
                float p0 = __shfl_xor_sync(0xffffffffu, a0, 1);
                float p1 = __shfl_xor_sync(0xffffffffu, a1, 1);
                float p2 = __shfl_xor_sync(0xffffffffu, a2, 1);
                float p3 = __shfl_xor_sync(0xffffffffu, a3, 1);
                if (evenq) {
                    int cl = c0 - cofs;              // multiple of 4 -> 16B aligned
                    if (rowA) red4(rowA + cl, a0, a1, p0, p1);
                    if (rowB) red4(rowB + cl, a2, a3, p2, p3);
                }
            }
        }
    }
}

// ---------------------------------------------------------------------------
// Kernel 2: MLP2. 64 nodes/CTA, 256 threads (8 warps, 2x4), warp tile 32x32.
// 2 CTAs/SM. Unchanged (known-good).
// ---------------------------------------------------------------------------
#define K2_XAH  0u
#define K2_XAL  16384u
#define K2_WH   32768u
#define K2_B1   65536u
#define K2_B2   66048u
#define K2_SMEM 66560u

__global__ void __launch_bounds__(256, 2) k_mlp2(
    const float* __restrict__ b2g, float* __restrict__ out, int NN)
{
    extern __shared__ char sm[];
    const u32 sb = s2u(sm);
    const int tid = threadIdx.x, wid = tid >> 5, l = tid & 31;
    const int lr8 = l & 7;
    const int g = l >> 2, q = l & 3;
    const int wm = (wid & 1) * 32, wn = (wid >> 1) * 32;
    const int n0 = blockIdx.x * 64;
    const u32 keyX = (u32)lr8 << 4;
    const u32 aCX = (u32)((l >> 4) & 1) * 16;
    const u32 bCX = (u32)((l >> 3) & 1) * 16;

    if (tid < 128) {
        ((float*)(sm + K2_B1))[tid] = g_nb1f[tid];
        ((float*)(sm + K2_B2))[tid] = b2g[tid];
    }

    // W1' resident (128 rows x 256B = 32K)
    #pragma unroll
    for (int i = 0; i < 8; ++i) {
        int idx = tid + i * 256;                      // 0..2047
        int n = idx >> 4, seg = idx & 15;
        u32 o = (u32)n * 256 + (u32)seg * 16;
        cpa16(sb + K2_WH + (o ^ (((u32)(n & 7)) << 4)), (const char*)g_nw1h + o);
    }
    CP_COMMIT();

    // nf tile [64,128] -> split fp16
    #pragma unroll
    for (int i = 0; i < 8; ++i) {
        int idx = tid + i * 256;
        int r = idx >> 5, c = (idx & 31) * 4;
        float4 v = make_float4(0.f, 0.f, 0.f, 0.f);
        if (n0 + r < NN) v = *reinterpret_cast<const float4*>(g_nf + (size_t)(n0 + r) * 128 + c);
        u32 h01, l01, h23, l23;
        splitpackh(v.x, v.y, h01, l01);
        splitpackh(v.z, v.w, h23, l23);
        u32 o = (u32)r * 256 + (((u32)c * 2) ^ (((u32)(r & 7)) << 4));
        sts64(sb + K2_XAH + o, h01, h23);
        sts64(sb + K2_XAL + o, l01, l23);
    }
    CP_WAIT0();
    __syncthreads();

    float acc[2][4][4];
    const u32 PA = K2_XAH + (u32)(wm + lr8 + ((l >> 3) & 1) * 8) * 256u + keyX;
    const u32 PB = K2_WH  + (u32)(wn + lr8 + ((l >> 4) & 1) * 8) * 256u + keyX;

    // ---- GEMM1 ----
    #pragma unroll
    for (int mt = 0; mt < 2; ++mt)
        #pragma unroll
        for (int nt = 0; nt < 4; ++nt)
            #pragma unroll
            for (int j = 0; j < 4; ++j) acc[mt][nt][j] = 0.f;

    #pragma unroll
    for (int kt = 0; kt < 8; ++kt) {
        u32 ca = (u32)kt * 32 + aCX, cb = (u32)kt * 32 + bCX;
        u32 Ah[2][4], Al[2][4];
        ldsm4(sb + ((PA)          ^ ca), Ah[0][0], Ah[0][1], Ah[0][2], Ah[0][3]);
        ldsm4(sb + ((PA + 4096u)  ^ ca), Ah[1][0], Ah[1][1], Ah[1][2], Ah[1][3]);
        ldsm4(sb + ((PA + 16384u) ^ ca), Al[0][0], Al[0][1], Al[0][2], Al[0][3]);
        ldsm4(sb + ((PA + 20480u) ^ ca), Al[1][0], Al[1][1], Al[1][2], Al[1][3]);
        #pragma unroll
        for (int ntg = 0; ntg < 2; ++ntg) {
            u32 bh[4];
            ldsm4(sb + ((PB + (u32)ntg * 4096u) ^ cb), bh[0], bh[1], bh[2], bh[3]);
            #pragma unroll
            for (int sub = 0; sub < 2; ++sub) {
                int nt = ntg * 2 + sub;
                #pragma unroll
                for (int mt = 0; mt < 2; ++mt) {
                    mma16816(acc[mt][nt], Ah[mt], bh[sub * 2], bh[sub * 2 + 1]);
                    mma16816(acc[mt][nt], Al[mt], bh[sub * 2], bh[sub * 2 + 1]);
                }
            }
        }
    }
    __syncthreads();

    // prefetch W2' over WH
    #pragma unroll
    for (int i = 0; i < 8; ++i) {
        int idx = tid + i * 256;
        int n = idx >> 4, seg = idx & 15;
        u32 o = (u32)n * 256 + (u32)seg * 16;
        cpa16(sb + K2_WH + (o ^ (((u32)(n & 7)) << 4)), (const char*)g_nw2h + o);
    }
    CP_COMMIT();

    // epilogue1 -> A2 over XA (stride 256B)
    {
        const float* b1s = (const float*)(sm + K2_B1);
        const u32 kr = (u32)g << 4;
        #pragma unroll
        for (int mt = 0; mt < 2; ++mt) {
            u32 row = (u32)(wm + mt * 16 + g);
            #pragma unroll
            for (int nt = 0; nt < 4; ++nt) {
                int c0 = wn + nt * 8 + q * 2;
                float bx = b1s[c0], by = b1s[c0 + 1];
                float f0 = fmaxf(acc[mt][nt][0] + bx, 0.f);
                float f1 = fmaxf(acc[mt][nt][1] + by, 0.f);
                float f2 = fmaxf(acc[mt][nt][2] + bx, 0.f);
                float f3 = fmaxf(acc[mt][nt][3] + by, 0.f);
                u32 col = ((u32)c0 * 2) ^ kr;
                u32 oA = row * 256 + col;
                u32 oB = (row + 8) * 256 + col;
                u32 hi, lo;
                splitpackh(f0, f1, hi, lo);
                sts32(sb + K2_XAH + oA, hi); sts32(sb + K2_XAL + oA, lo);
                splitpackh(f2, f3, hi, lo);
                sts32(sb + K2_XAH + oB, hi); sts32(sb + K2_XAL + oB, lo);
            }
        }
    }
    CP_WAIT0();
    __syncthreads();

    // ---- GEMM2 ----
    #pragma unroll
    for (int mt = 0; mt < 2; ++mt)
        #pragma unroll
        for (int nt = 0; nt < 4; ++nt)
            #pragma unroll
            for (int j = 0; j < 4; ++j) acc[mt][nt][j] = 0.f;

    #pragma unroll
    for (int kt = 0; kt < 8; ++kt) {
        u32 ca = (u32)kt * 32 + aCX, cb = (u32)kt * 32 + bCX;
        u32 Ah[2][4], Al[2][4];
        ldsm4(sb + ((PA)          ^ ca), Ah[0][0], Ah[0][1], Ah[0][2], Ah[0][3]);
        ldsm4(sb + ((PA + 4096u)  ^ ca), Ah[1][0], Ah[1][1], Ah[1][2], Ah[1][3]);
        ldsm4(sb + ((PA + 16384u) ^ ca), Al[0][0], Al[0][1], Al[0][2], Al[0][3]);
        ldsm4(sb + ((PA + 20480u) ^ ca), Al[1][0], Al[1][1], Al[1][2], Al[1][3]);
        #pragma unroll
        for (int ntg = 0; ntg < 2; ++ntg) {
            u32 bh[4];
            ldsm4(sb + ((PB + (u32)ntg * 4096u) ^ cb), bh[0], bh[1], bh[2], bh[3]);
            #pragma unroll
            for (int sub = 0; sub < 2; ++sub) {
                int nt = ntg * 2 + sub;
                #pragma unroll
                for (int mt = 0; mt < 2; ++mt) {
                    mma16816(acc[mt][nt], Ah[mt], bh[sub * 2], bh[sub * 2 + 1]);
                    mma16816(acc[mt][nt], Al[mt], bh[sub * 2], bh[sub * 2 + 1]);
                }
            }
        }
    }

    // output
    {
        const float* b2s = (const float*)(sm + K2_B2);
        #pragma unroll
        for (int mt = 0; mt < 2; ++mt) {
            int rA = n0 + wm + mt * 16 + g;
            int rB = rA + 8;
            #pragma unroll
            for (int nt = 0; nt < 4; ++nt) {
                int c0 = wn + nt * 8 + q * 2;
                float bx = b2s[c0], by = b2s[c0 + 1];
                if (rA < NN)
                    *reinterpret_cast<float2*>(out + (size_t)rA * 128 + c0) =
                        make_float2(acc[mt][nt][0] + bx, acc[mt][nt][1] + by);
                if (rB < NN)
                    *reinterpret_cast<float2*>(out + (size_t)rB * 128 + c0) =
                        make_float2(acc[mt][nt][2] + bx, acc[mt][nt][3] + by);
            }
        }
    }
}

// ---------------------------------------------------------------------------
extern "C" void kernel_launch(void* const* d_in, const int* in_sizes, int n_in,
                              void* d_out, int out_size) {
    const float* x    = (const float*)d_in[0];
    const int*   tok  = (const int*)d_in[3];   // int32 (JAX x64 disabled)
    const float* op_g  = (const float*)d_in[4];
    const float* op_b  = (const float*)d_in[5];
    const float* op_m  = (const float*)d_in[6];
    const float* op_v  = (const float*)d_in[7];
    const float* op_w1 = (const float*)d_in[8];
    const float* op_b1 = (const float*)d_in[9];
    const float* op_w2 = (const float*)d_in[10];
    const float* op_b2 = (const float*)d_in[11];
    const float* nm_g  = (const float*)d_in[12];
    const float* nm_b  = (const float*)d_in[13];
    const float* nm_m  = (const float*)d_in[14];
    const float* nm_v  = (const float*)d_in[15];
    const float* nm_w1 = (const float*)d_in[16];
    const float* nm_b1 = (const float*)d_in[17];
    const float* nm_w2 = (const float*)d_in[18];
    const float* nm_b2 = (const float*)d_in[19];

    int T  = in_sizes[0] / 128;
    int NN = in_sizes[2];
    float* out = (float*)d_out;

    cudaFuncSetAttribute(k_mlp1, cudaFuncAttributeMaxDynamicSharedMemorySize, K1_SMEM);
    cudaFuncSetAttribute(k_mlp2, cudaFuncAttributeMaxDynamicSharedMemorySize, K2_SMEM);

    int n4 = (NN * 128) / 4;
    k_zero<<<(n4 + 255) / 256, 256>>>(n4);

    k_prep<<<560, 256>>>(op_w1, op_g, op_v, op_w2, nm_w1, nm_g, nm_v, nm_w2,
                         op_b1, op_b, op_m, nm_b1, nm_b, nm_m);

    k_mlp1<<<(T + 63) / 64, 256, K1_SMEM>>>(x, tok, op_b2, T);
    k_mlp2<<<(NN + 63) / 64, 256, K2_SMEM>>>(nm_b2, out, NN);
}

// round 13
// speedup vs baseline: 11.8968x; 1.1641x over previous
#include <cuda_runtime.h>
#include <cuda_fp16.h>
#include <cstdint>

typedef unsigned int u32;
typedef unsigned long long u64;

#define NMAX 100000

// ---------------- persistent scratch ----------------
__device__ float g_nf[NMAX * 128];
__device__ __align__(16) __half g_w1h[256 * 128];    // BN-folded, fp16 RN
__device__ __align__(16) __half g_w2h[256 * 256];
__device__ __align__(16) __half g_nw1h[128 * 128];   // BN-folded
__device__ __align__(16) __half g_nw2h[128 * 128];
__device__ float g_b1f[256];
__device__ float g_nb1f[128];

// ---------------- helpers ----------------
__device__ __forceinline__ u32 s2u(const void* p) {
    u32 a;
    asm("{ .reg .u64 t; cvta.to.shared.u64 t, %1; cvt.u32.u64 %0, t; }" : "=r"(a) : "l"(p));
    return a;
}
__device__ __forceinline__ void ldsm4(u32 a, u32& r0, u32& r1, u32& r2, u32& r3) {
    asm volatile("ldmatrix.sync.aligned.m8n8.x4.shared.b16 {%0,%1,%2,%3}, [%4];"
                 : "=r"(r0), "=r"(r1), "=r"(r2), "=r"(r3) : "r"(a));
}
__device__ __forceinline__ void sts32(u32 a, u32 v) {
    asm volatile("st.shared.b32 [%0], %1;" :: "r"(a), "r"(v));
}
__device__ __forceinline__ void sts64(u32 a, u32 x, u32 y) {
    asm volatile("st.shared.v2.b32 [%0], {%1,%2};" :: "r"(a), "r"(x), "r"(y));
}
__device__ __forceinline__ void cpa16(u32 dst, const void* src) {
    asm volatile("cp.async.cg.shared.global [%0], [%1], 16;" :: "r"(dst), "l"(src));
}
#define CP_COMMIT() asm volatile("cp.async.commit_group;")
#define CP_WAIT0()  asm volatile("cp.async.wait_group 0;")

__device__ __forceinline__ void mma16816(float* d, const u32* a, u32 b0, u32 b1) {
    asm volatile(
        "mma.sync.aligned.m16n8k16.row.col.f32.f16.f16.f32 "
        "{%0,%1,%2,%3}, {%4,%5,%6,%7}, {%8,%9}, {%0,%1,%2,%3};"
        : "+f"(d[0]), "+f"(d[1]), "+f"(d[2]), "+f"(d[3])
        : "r"(a[0]), "r"(a[1]), "r"(a[2]), "r"(a[3]), "r"(b0), "r"(b1));
}
__device__ __forceinline__ void red4(float* p, float a, float b, float c, float d) {
    asm volatile("red.global.add.v4.f32 [%0], {%1,%2,%3,%4};"
                 :: "l"(p), "f"(a), "f"(b), "f"(c), "f"(d) : "memory");
}
__device__ __forceinline__ u32 pack2h(__half a, __half b) {
    return (u32)__half_as_ushort(a) | ((u32)__half_as_ushort(b) << 16);
}

// ---------------- prep ----------------
__global__ void k_zero(int n4) {
    int i = blockIdx.x * blockDim.x + threadIdx.x;
    if (i < n4) reinterpret_cast<float4*>(g_nf)[i] = make_float4(0.f, 0.f, 0.f, 0.f);
}
// blocks [0,512): weight convert; blocks [512,560): bias folding
__global__ void k_prep(const float* __restrict__ W1, const float* __restrict__ og,
                       const float* __restrict__ ov, const float* __restrict__ W2,
                       const float* __restrict__ NW1, const float* __restrict__ ng,
                       const float* __restrict__ nv, const float* __restrict__ NW2,
                       const float* __restrict__ ob1, const float* __restrict__ ob,
                       const float* __restrict__ om, const float* __restrict__ nb1,
                       const float* __restrict__ nb, const float* __restrict__ nm) {
    int blk = blockIdx.x;
    if (blk < 512) {
        int i = blk * 256 + threadIdx.x;
        if (i < 32768) {
            int k = i & 127;
            g_w1h[i] = __float2half_rn(W1[i] * (og[k] * rsqrtf(ov[k] + 1e-5f)));
        } else if (i < 98304) {
            int j = i - 32768;
            g_w2h[j] = __float2half_rn(W2[j]);
        } else if (i < 114688) {
            int j = i - 98304;
            int k = j & 127;
            g_nw1h[j] = __float2half_rn(NW1[j] * (ng[k] * rsqrtf(nv[k] + 1e-5f)));
        } else {
            int j = i - 114688;
            g_nw2h[j] = __float2half_rn(NW2[j]);
        }
    } else {
        int job = (blk - 512) * 8 + (threadIdx.x >> 5);
        int lane = threadIdx.x & 31;
        if (job < 256) {
            float s = 0.f;
            for (int k = lane; k < 128; k += 32) {
                float sc = og[k] * rsqrtf(ov[k] + 1e-5f);
                s += W1[job * 128 + k] * (ob[k] - om[k] * sc);
            }
            for (int o = 16; o; o >>= 1) s += __shfl_xor_sync(~0u, s, o);
            if (lane == 0) g_b1f[job] = ob1[job] + s;
        } else if (job < 384) {
            int n = job - 256;
            float s = 0.f;
            for (int k = lane; k < 128; k += 32) {
                float sc = ng[k] * rsqrtf(nv[k] + 1e-5f);
                s += NW1[n * 128 + k] * (nb[k] - nm[k] * sc);
            }
            for (int o = 16; o; o >>= 1) s += __shfl_xor_sync(~0u, s, o);
            if (lane == 0) g_nb1f[n] = nb1[n] + s;
        }
    }
}

// ---------------------------------------------------------------------------
// Kernel 1: MLP1 + scatter. 64 tokens/CTA, 256 threads (8 warps, 2x4),
// warp tile 32x64, 2 CTAs/SM. Pure fp16 1-term GEMMs (weight+activation
// rounding errors verified quadrature-additive, total ~5e-4 < 1e-3).
// phase1: XAH 0(16K) W1H 16K(64K)
// phase2: A2H 0(32K) BUF0 32K(32K,k=64 slab) BUF1 64K(32K)
// ---------------------------------------------------------------------------
#define K1_XAH   0u
#define K1_W1H   16384u
#define K1_A2H   0u
#define K1_BUF0  32768u
#define K1_BUF1  65536u
#define K1_B1    98304u
#define K1_B2    99328u
#define K1_SMEM  100352u

__global__ void __launch_bounds__(256, 2) k_mlp1(
    const float* __restrict__ x, const int* __restrict__ tok,
    const float* __restrict__ b2g, int T)
{
    extern __shared__ char sm[];
    const u32 sb = s2u(sm);
    const int tid = threadIdx.x, wid = tid >> 5, l = tid & 31;
    const int lr8 = l & 7;
    const int g = l >> 2, q = l & 3;
    const int wm = (wid & 1) * 32, wn = (wid >> 1) * 64;
    const int t0 = blockIdx.x * 64;
    const u32 keyX = (u32)lr8 << 4;
    const u32 aCX = (u32)((l >> 4) & 1) * 16;
    const u32 bCX = (u32)((l >> 3) & 1) * 16;

    ((float*)(sm + K1_B1))[tid] = g_b1f[tid];
    ((float*)(sm + K1_B2))[tid] = b2g[tid];

    // W1 resident (fp16, 256 rows x 256B = 64K)
    #pragma unroll
    for (int i = 0; i < 16; ++i) {
        int idx = tid + i * 256;                     // 0..4095
        int n = idx >> 4, seg = idx & 15;
        u32 o = (u32)n * 256 + (u32)seg * 16;
        cpa16(sb + K1_W1H + (o ^ (((u32)(n & 7)) << 4)), (const char*)g_w1h + o);
    }
    CP_COMMIT();

    // x tile [64,128] -> fp16 (hi only)
    #pragma unroll
    for (int i = 0; i < 8; ++i) {
        int idx = tid + i * 256;                     // float4 0..2047
        int r = idx >> 5, c = (idx & 31) * 4;
        float4 v = make_float4(0.f, 0.f, 0.f, 0.f);
        if (t0 + r < T) v = *reinterpret_cast<const float4*>(x + (size_t)(t0 + r) * 128 + c);
        u32 h01 = pack2h(__float2half_rn(v.x), __float2half_rn(v.y));
        u32 h23 = pack2h(__float2half_rn(v.z), __float2half_rn(v.w));
        u32 o = (u32)r * 256 + (((u32)c * 2) ^ (((u32)(r & 7)) << 4));
        sts64(sb + K1_XAH + o, h01, h23);
    }
    CP_WAIT0();
    __syncthreads();

    // ---------------- GEMM1: y1 = x @ W1^T (1-term) ----------------
    float acc[2][8][4];
    #pragma unroll
    for (int mt = 0; mt < 2; ++mt)
        #pragma unroll
        for (int nt = 0; nt < 8; ++nt)
            #pragma unroll
            for (int j = 0; j < 4; ++j) acc[mt][nt][j] = 0.f;

    {
        const u32 PA = K1_XAH + (u32)(wm + lr8 + ((l >> 3) & 1) * 8) * 256u + keyX;
        const u32 PB = K1_W1H + (u32)(wn + lr8 + ((l >> 4) & 1) * 8) * 256u + keyX;
        #pragma unroll
        for (int kt = 0; kt < 8; ++kt) {
            u32 ca = (u32)kt * 32 + aCX, cb = (u32)kt * 32 + bCX;
            u32 Ah[2][4];
            ldsm4(sb + ((PA)         ^ ca), Ah[0][0], Ah[0][1], Ah[0][2], Ah[0][3]);
            ldsm4(sb + ((PA + 4096u) ^ ca), Ah[1][0], Ah[1][1], Ah[1][2], Ah[1][3]);
            #pragma unroll
            for (int ntg = 0; ntg < 4; ++ntg) {
                u32 bh[4];
                ldsm4(sb + ((PB + (u32)ntg * 4096u) ^ cb), bh[0], bh[1], bh[2], bh[3]);
                #pragma unroll
                for (int sub = 0; sub < 2; ++sub) {
                    int nt = ntg * 2 + sub;
                    #pragma unroll
                    for (int mt = 0; mt < 2; ++mt)
                        mma16816(acc[mt][nt], Ah[mt], bh[sub * 2], bh[sub * 2 + 1]);
                }
            }
        }
    }
    __syncthreads();   // GEMM1 reads done; XA + W1H regions reusable

    // prefetch W2 slab 0 (k 0..63): 256 rows x 128B = 32K -> BUF0
    #pragma unroll
    for (int i = 0; i < 8; ++i) {
        int idx = tid + i * 256;                     // 0..2047
        int n = idx >> 3, seg = idx & 7;
        u32 o = (u32)n * 128 + (u32)seg * 16;
        cpa16(sb + K1_BUF0 + (o ^ (((u32)(n & 7)) << 4)),
              (const char*)g_w2h + (size_t)n * 512 + (size_t)seg * 16);
    }
    CP_COMMIT();

    // epilogue1: A2 = fp16(relu(y1 + b1f)), 64 rows x 512B
    {
        const float* b1s = (const float*)(sm + K1_B1);
        const u32 kr = (u32)g << 4;
        #pragma unroll
        for (int mt = 0; mt < 2; ++mt) {
            u32 row = (u32)(wm + mt * 16 + g);
            #pragma unroll
            for (int nt = 0; nt < 8; ++nt) {
                int c0 = wn + nt * 8 + q * 2;
                float bx = b1s[c0], by = b1s[c0 + 1];
                float f0 = fmaxf(acc[mt][nt][0] + bx, 0.f);
                float f1 = fmaxf(acc[mt][nt][1] + by, 0.f);
                float f2 = fmaxf(acc[mt][nt][2] + bx, 0.f);
                float f3 = fmaxf(acc[mt][nt][3] + by, 0.f);
                u32 col = ((u32)c0 * 2) ^ kr;
                sts32(sb + K1_A2H + row * 512 + col,
                      pack2h(__float2half_rn(f0), __float2half_rn(f1)));
                sts32(sb + K1_A2H + (row + 8) * 512 + col,
                      pack2h(__float2half_rn(f2), __float2half_rn(f3)));
            }
        }
    }
    CP_WAIT0();
    __syncthreads();

    // ---------------- GEMM2: y2 = A2 @ W2^T (K=256, 4 slabs of 64) ----
    #pragma unroll
    for (int mt = 0; mt < 2; ++mt)
        #pragma unroll
        for (int nt = 0; nt < 8; ++nt)
            #pragma unroll
            for (int j = 0; j < 4; ++j) acc[mt][nt][j] = 0.f;

    {
        const u32 PA2 = K1_A2H + (u32)(wm + lr8 + ((l >> 3) & 1) * 8) * 512u + keyX;
        const u32 PW2 = ((u32)(wn + lr8 + ((l >> 4) & 1) * 8) * 128u) ^ keyX;
        #pragma unroll 1
        for (int s = 0; s < 4; ++s) {
            if (s < 3) {
                u32 dB = (s & 1) ? K1_BUF0 : K1_BUF1;
                #pragma unroll
                for (int i = 0; i < 8; ++i) {
                    int idx = tid + i * 256;
                    int n = idx >> 3, seg = idx & 7;
                    u32 o = (u32)n * 128 + (u32)seg * 16;
                    size_t src = (size_t)n * 512 + (size_t)(s + 1) * 128 + (size_t)seg * 16;
                    cpa16(sb + dB + (o ^ (((u32)(n & 7)) << 4)), (const char*)g_w2h + src);
                }
                CP_COMMIT();
            }
            u32 bB = sb + ((s & 1) ? K1_BUF1 : K1_BUF0);
            #pragma unroll
            for (int ktL = 0; ktL < 4; ++ktL) {
                int kt = s * 4 + ktL;
                u32 ca = (u32)kt * 32 + aCX;
                u32 cw = (u32)ktL * 32 + bCX;
                u32 Ah[2][4];
                ldsm4(sb + ((PA2)         ^ ca), Ah[0][0], Ah[0][1], Ah[0][2], Ah[0][3]);
                ldsm4(sb + ((PA2 + 8192u) ^ ca), Ah[1][0], Ah[1][1], Ah[1][2], Ah[1][3]);
                #pragma unroll
                for (int ntg = 0; ntg < 4; ++ntg) {
                    u32 bh[4];
                    ldsm4(bB + ((PW2 + (u32)ntg * 2048u) ^ cw), bh[0], bh[1], bh[2], bh[3]);
                    #pragma unroll
                    for (int sub = 0; sub < 2; ++sub) {
                        int nt = ntg * 2 + sub;
                        #pragma unroll
                        for (int mt = 0; mt < 2; ++mt)
                            mma16816(acc[mt][nt], Ah[mt], bh[sub * 2], bh[sub * 2 + 1]);
                    }
                }
            }
            if (s < 3) CP_WAIT0();
            __syncthreads();
        }
    }

    // ---------------- scatter: v4 via lane-pair merge ----------------
    {
        const float* b2s = (const float*)(sm + K1_B2);
        int cofs = (wn < 128) ? 0 : 128;
        const bool evenq = ((q & 1) == 0);
        #pragma unroll
        for (int mt = 0; mt < 2; ++mt) {
            int tA = t0 + wm + mt * 16 + g;
            int tB = tA + 8;
            float* rowA = nullptr; float* rowB = nullptr;
            if (tA < T) {
                int nd = (cofs == 0) ? tok[tA] : tok[T + tA];
                rowA = g_nf + (size_t)nd * 128;
            }
            if (tB < T) {
                int nd = (cofs == 0) ? tok[tB] : tok[T + tB];
                rowB = g_nf + (size_t)nd * 128;
            }
            #pragma unroll
            for (int nt = 0; nt < 8; ++nt) {
                int c0 = wn + nt * 8 + q * 2;
                float bx = b2s[c0], by = b2s[c0 + 1];
                float a0 = acc[mt][nt][0] + bx;
                float a1 = acc[mt][nt][1] + by;
                float a2 = acc[mt][nt][2] + bx;
                float a3 = acc[mt][nt][3] + by;
                float p0 = __shfl_xor_sync(0xffffffffu, a0, 1);
                float p1 = __shfl_xor_sync(0xffffffffu, a1, 1);
                float p2 = __shfl_xor_sync(0xffffffffu, a2, 1);
                float p3 = __shfl_xor_sync(0xffffffffu, a3, 1);
                if (evenq) {
                    int cl = c0 - cofs;              // multiple of 4 -> 16B aligned
                    if (rowA) red4(rowA + cl, a0, a1, p0, p1);
                    if (rowB) red4(rowB + cl, a2, a3, p2, p3);
                }
            }
        }
    }
}

// ---------------------------------------------------------------------------
// Kernel 2: MLP2. 64 nodes/CTA, 256 threads (8 warps, 2x4), warp tile 32x32.
// Pure fp16 1-term GEMMs. XAH 0(16K) WH 16K(32K)
// ---------------------------------------------------------------------------
#define K2_XAH  0u
#define K2_WH   16384u
#define K2_B1   49152u
#define K2_B2   49664u
#define K2_SMEM 50176u

__global__ void __launch_bounds__(256, 2) k_mlp2(
    const float* __restrict__ b2g, float* __restrict__ out, int NN)
{
    extern __shared__ char sm[];
    const u32 sb = s2u(sm);
    const int tid = threadIdx.x, wid = tid >> 5, l = tid & 31;
    const int lr8 = l & 7;
    const int g = l >> 2, q = l & 3;
    const int wm = (wid & 1) * 32, wn = (wid >> 1) * 32;
    const int n0 = blockIdx.x * 64;
    const u32 keyX = (u32)lr8 << 4;
    const u32 aCX = (u32)((l >> 4) & 1) * 16;
    const u32 bCX = (u32)((l >> 3) & 1) * 16;

    if (tid < 128) {
        ((float*)(sm + K2_B1))[tid] = g_nb1f[tid];
        ((float*)(sm + K2_B2))[tid] = b2g[tid];
    }

    // W1' resident (128 rows x 256B = 32K)
    #pragma unroll
    for (int i = 0; i < 8; ++i) {
        int idx = tid + i * 256;                      // 0..2047
        int n = idx >> 4, seg = idx & 15;
        u32 o = (u32)n * 256 + (u32)seg * 16;
        cpa16(sb + K2_WH + (o ^ (((u32)(n & 7)) << 4)), (const char*)g_nw1h + o);
    }
    CP_COMMIT();

    // nf tile [64,128] -> fp16 (hi only)
    #pragma unroll
    for (int i = 0; i < 8; ++i) {
        int idx = tid + i * 256;
        int r = idx >> 5, c = (idx & 31) * 4;
        float4 v = make_float4(0.f, 0.f, 0.f, 0.f);
        if (n0 + r < NN) v = *reinterpret_cast<const float4*>(g_nf + (size_t)(n0 + r) * 128 + c);
        u32 h01 = pack2h(__float2half_rn(v.x), __float2half_rn(v.y));
        u32 h23 = pack2h(__float2half_rn(v.z), __float2half_rn(v.w));
        u32 o = (u32)r * 256 + (((u32)c * 2) ^ (((u32)(r & 7)) << 4));
        sts64(sb + K2_XAH + o, h01, h23);
    }
    CP_WAIT0();
    __syncthreads();

    float acc[2][4][4];
    const u32 PA = K2_XAH + (u32)(wm + lr8 + ((l >> 3) & 1) * 8) * 256u + keyX;
    const u32 PB = K2_WH  + (u32)(wn + lr8 + ((l >> 4) & 1) * 8) * 256u + keyX;

    // ---- GEMM1 (1-term) ----
    #pragma unroll
    for (int mt = 0; mt < 2; ++mt)
        #pragma unroll
        for (int nt = 0; nt < 4; ++nt)
            #pragma unroll
            for (int j = 0; j < 4; ++j) acc[mt][nt][j] = 0.f;

    #pragma unroll
    for (int kt = 0; kt < 8; ++kt) {
        u32 ca = (u32)kt * 32 + aCX, cb = (u32)kt * 32 + bCX;
        u32 Ah[2][4];
        ldsm4(sb + ((PA)         ^ ca), Ah[0][0], Ah[0][1], Ah[0][2], Ah[0][3]);
        ldsm4(sb + ((PA + 4096u) ^ ca), Ah[1][0], Ah[1][1], Ah[1][2], Ah[1][3]);
        #pragma unroll
        for (int ntg = 0; ntg < 2; ++ntg) {
            u32 bh[4];
            ldsm4(sb + ((PB + (u32)ntg * 4096u) ^ cb), bh[0], bh[1], bh[2], bh[3]);
            #pragma unroll
            for (int sub = 0; sub < 2; ++sub) {
                int nt = ntg * 2 + sub;
                #pragma unroll
                for (int mt = 0; mt < 2; ++mt)
                    mma16816(acc[mt][nt], Ah[mt], bh[sub * 2], bh[sub * 2 + 1]);
            }
        }
    }
    __syncthreads();

    // prefetch W2' over WH
    #pragma unroll
    for (int i = 0; i < 8; ++i) {
        int idx = tid + i * 256;
        int n = idx >> 4, seg = idx & 15;
        u32 o = (u32)n * 256 + (u32)seg * 16;
        cpa16(sb + K2_WH + (o ^ (((u32)(n & 7)) << 4)), (const char*)g_nw2h + o);
    }
    CP_COMMIT();

    // epilogue1 -> A2 over XA (stride 256B, hi only)
    {
        const float* b1s = (const float*)(sm + K2_B1);
        const u32 kr = (u32)g << 4;
        #pragma unroll
        for (int mt = 0; mt < 2; ++mt) {
            u32 row = (u32)(wm + mt * 16 + g);
            #pragma unroll
            for (int nt = 0; nt < 4; ++nt) {
                int c0 = wn + nt * 8 + q * 2;
                float bx = b1s[c0], by = b1s[c0 + 1];
                float f0 = fmaxf(acc[mt][nt][0] + bx, 0.f);
                float f1 = fmaxf(acc[mt][nt][1] + by, 0.f);
                float f2 = fmaxf(acc[mt][nt][2] + bx, 0.f);
                float f3 = fmaxf(acc[mt][nt][3] + by, 0.f);
                u32 col = ((u32)c0 * 2) ^ kr;
                sts32(sb + K2_XAH + row * 256 + col,
                      pack2h(__float2half_rn(f0), __float2half_rn(f1)));
                sts32(sb + K2_XAH + (row + 8) * 256 + col,
                      pack2h(__float2half_rn(f2), __float2half_rn(f3)));
            }
        }
    }
    CP_WAIT0();
    __syncthreads();

    // ---- GEMM2 (1-term) ----
    #pragma unroll
    for (int mt = 0; mt < 2; ++mt)
        #pragma unroll
        for (int nt = 0; nt < 4; ++nt)
            #pragma unroll
            for (int j = 0; j < 4; ++j) acc[mt][nt][j] = 0.f;

    #pragma unroll
    for (int kt = 0; kt < 8; ++kt) {
        u32 ca = (u32)kt * 32 + aCX, cb = (u32)kt * 32 + bCX;
        u32 Ah[2][4];
        ldsm4(sb + ((PA)         ^ ca), Ah[0][0], Ah[0][1], Ah[0][2], Ah[0][3]);
        ldsm4(sb + ((PA + 4096u) ^ ca), Ah[1][0], Ah[1][1], Ah[1][2], Ah[1][3]);
        #pragma unroll
        for (int ntg = 0; ntg < 2; ++ntg) {
            u32 bh[4];
            ldsm4(sb + ((PB + (u32)ntg * 4096u) ^ cb), bh[0], bh[1], bh[2], bh[3]);
            #pragma unroll
            for (int sub = 0; sub < 2; ++sub) {
                int nt = ntg * 2 + sub;
                #pragma unroll
                for (int mt = 0; mt < 2; ++mt)
                    mma16816(acc[mt][nt], Ah[mt], bh[sub * 2], bh[sub * 2 + 1]);
            }
        }
    }

    // output
    {
        const float* b2s = (const float*)(sm + K2_B2);
        #pragma unroll
        for (int mt = 0; mt < 2; ++mt) {
            int rA = n0 + wm + mt * 16 + g;
            int rB = rA + 8;
            #pragma unroll
            for (int nt = 0; nt < 4; ++nt) {
                int c0 = wn + nt * 8 + q * 2;
                float bx = b2s[c0], by = b2s[c0 + 1];
                if (rA < NN)
                    *reinterpret_cast<float2*>(out + (size_t)rA * 128 + c0) =
                        make_float2(acc[mt][nt][0] + bx, acc[mt][nt][1] + by);
                if (rB < NN)
                    *reinterpret_cast<float2*>(out + (size_t)rB * 128 + c0) =
                        make_float2(acc[mt][nt][2] + bx, acc[mt][nt][3] + by);
            }
        }
    }
}

// ---------------------------------------------------------------------------
extern "C" void kernel_launch(void* const* d_in, const int* in_sizes, int n_in,
                              void* d_out, int out_size) {
    const float* x    = (const float*)d_in[0];
    const int*   tok  = (const int*)d_in[3];   // int32 (JAX x64 disabled)
    const float* op_g  = (const float*)d_in[4];
    const float* op_b  = (const float*)d_in[5];
    const float* op_m  = (const float*)d_in[6];
    const float* op_v  = (const float*)d_in[7];
    const float* op_w1 = (const float*)d_in[8];
    const float* op_b1 = (const float*)d_in[9];
    const float* op_w2 = (const float*)d_in[10];
    const float* op_b2 = (const float*)d_in[11];
    const float* nm_g  = (const float*)d_in[12];
    const float* nm_b  = (const float*)d_in[13];
    const float* nm_m  = (const float*)d_in[14];
    const float* nm_v  = (const float*)d_in[15];
    const float* nm_w1 = (const float*)d_in[16];
    const float* nm_b1 = (const float*)d_in[17];
    const float* nm_w2 = (const float*)d_in[18];
    const float* nm_b2 = (const float*)d_in[19];

    int T  = in_sizes[0] / 128;
    int NN = in_sizes[2];
    float* out = (float*)d_out;

    cudaFuncSetAttribute(k_mlp1, cudaFuncAttributeMaxDynamicSharedMemorySize, K1_SMEM);
    cudaFuncSetAttribute(k_mlp2, cudaFuncAttributeMaxDynamicSharedMemorySize, K2_SMEM);

    int n4 = (NN * 128) / 4;
    k_zero<<<(n4 + 255) / 256, 256>>>(n4);

    k_prep<<<560, 256>>>(op_w1, op_g, op_v, op_w2, nm_w1, nm_g, nm_v, nm_w2,
                         op_b1, op_b, op_m, nm_b1, nm_b, nm_m);

    k_mlp1<<<(T + 63) / 64, 256, K1_SMEM>>>(x, tok, op_b2, T);
    k_mlp2<<<(NN + 63) / 64, 256, K2_SMEM>>>(nm_b2, out, NN);
}